// round 4
// baseline (speedup 1.0000x reference)
#include <cuda_runtime.h>
#include <cuda_fp16.h>
#include <cstdint>

typedef unsigned long long ull;

#define OBS_DIMV 4096
#define NGVF     4096
#define NA       18
#define ROWS     16
#define THREADS  512
#define NWARP    16
#define PAIRS    8
#define OSTRIDE_H2 4100     /* half2 slots per obs row-pair */

/* smem layout (floats) */
#define OBS_FLOATS (PAIRS * OSTRIDE_H2)            /* 32800 */
#define P_OFF      OBS_FLOATS
#define P_FLOATS   (NWARP * ROWS * 9 * 2)          /* 4608  */
#define POBS_OFF   (P_OFF + P_FLOATS)
#define POBS_FLOATS (NWARP * 9 * 2)                /* 288   */
#define SMEM_FLOATS (POBS_OFF + POBS_FLOATS)
#define SMEM_BYTES  (SMEM_FLOATS * 4)              /* 150784 B */

/* repacked weights (device scratch, written every launch by repack_kernel) */
__device__ float Wpk_g[(size_t)NGVF * 128];   /* [g][p=hpair][i][2]        */
__device__ float Qpk_g[(size_t)NGVF * 144];   /* [g][a2][h][2]             */
__device__ float Qobs_g[9 * OBS_DIMV * 2];    /* [a2][j][2]                */
__device__ int   Idx4_g[NGVF * 16];           /* gather byte offsets (idx*4) */

#define N_W  524288
#define N_Q  589824
#define N_QO 73728
#define N_I  65536
#define N_TOT (N_W + N_Q + N_QO + N_I)        /* 1253376 */

__global__ void repack_kernel(const float* __restrict__ gvfW,
                              const float* __restrict__ qW,
                              const int*   __restrict__ gidx)
{
    int id = blockIdx.x * 256 + threadIdx.x;
    if (id < N_W) {
        int g = id >> 7, r = id & 127;
        int p = r >> 5, q = r & 31, i = q >> 1, s = q & 1;
        Wpk_g[id] = gvfW[g * 128 + (2 * p + s) * 16 + i];
    } else if (id < N_W + N_Q) {
        int t = id - N_W;
        int g = t / 144, r = t - g * 144;
        int a2 = r >> 4, q = r & 15, h = q >> 1, s = q & 1;
        Qpk_g[t] = qW[(size_t)(2 * a2 + s) * (OBS_DIMV + NGVF * 8)
                      + OBS_DIMV + (size_t)g * 8 + h];
    } else if (id < N_W + N_Q + N_QO) {
        int t = id - (N_W + N_Q);
        int a2 = t >> 13, r = t & 8191, j = r >> 1, s = r & 1;
        Qobs_g[t] = qW[(size_t)(2 * a2 + s) * (OBS_DIMV + NGVF * 8) + j];
    } else if (id < N_TOT) {
        int t = id - (N_W + N_Q + N_QO);
        Idx4_g[t] = gidx[t] * 4;
    }
}

/* ---- f32x2 helpers ---- */
__device__ __forceinline__ ull pack2(float a, float b) {
    ull r; asm("mov.b64 %0,{%1,%2};" : "=l"(r) : "f"(a), "f"(b)); return r;
}
__device__ __forceinline__ float2 unpack2(ull v) {
    float2 f; asm("mov.b64 {%0,%1},%2;" : "=f"(f.x), "=f"(f.y) : "l"(v)); return f;
}
__device__ __forceinline__ void ffma2(ull& d, ull a, ull b) {
    asm("fma.rn.f32x2 %0,%1,%2,%0;" : "+l"(d) : "l"(a), "l"(b));
}
__device__ __forceinline__ ull addf2(ull a, ull b) {
    ull r; asm("add.rn.f32x2 %0,%1,%2;" : "=l"(r) : "l"(a), "l"(b)); return r;
}
__device__ __forceinline__ ull gpk(const char* ob, int off) {
    float v = __half2float(*(const __half*)(ob + off));
    return pack2(v, v);
}

extern __shared__ float smf[];

__global__ void __launch_bounds__(THREADS, 1)
nibbler_main(const float* __restrict__ obs, float* __restrict__ out)
{
    const int tid  = threadIdx.x;
    const int w    = tid >> 5;
    const int lane = tid & 31;
    const int gpar = lane & 1;
    const int row  = lane >> 1;
    const int pair = row >> 1;
    const int rh   = row & 1;
    const int r0   = blockIdx.x * ROWS;

    /* stage 16 obs rows into smem as fp16 half2 row-pairs */
    {
        __half2* sObs = reinterpret_cast<__half2*>(smf);
        #pragma unroll 4
        for (int id = tid; id < PAIRS * (OBS_DIMV / 4); id += THREADS) {
            int p = id >> 10, j = id & 1023;
            float4 va = *(const float4*)(obs + (size_t)(r0 + 2 * p    ) * OBS_DIMV + j * 4);
            float4 vb = *(const float4*)(obs + (size_t)(r0 + 2 * p + 1) * OBS_DIMV + j * 4);
            __half2 h0 = __floats2half2_rn(va.x, vb.x);
            __half2 h1 = __floats2half2_rn(va.y, vb.y);
            __half2 h2 = __floats2half2_rn(va.z, vb.z);
            __half2 h3 = __floats2half2_rn(va.w, vb.w);
            uint4 pk;
            pk.x = *reinterpret_cast<uint32_t*>(&h0);
            pk.y = *reinterpret_cast<uint32_t*>(&h1);
            pk.z = *reinterpret_cast<uint32_t*>(&h2);
            pk.w = *reinterpret_cast<uint32_t*>(&h3);
            *(uint4*)(sObs + p * OSTRIDE_H2 + j * 4) = pk;
        }
    }
    __syncthreads();

    const char* ob = (const char*)smf + pair * (OSTRIDE_H2 * 4) + rh * 2;

    ull acc2[9];
    #pragma unroll
    for (int a = 0; a < 9; ++a) acc2[a] = 0ull;

    /* main loop: warp w, parity gpar covers gvfs g = 2w + 32*it + gpar */
    #pragma unroll 1
    for (int it = 0; it < 128; ++it) {
        const int g = 2 * w + 32 * it + gpar;

        const int4* Ip = (const int4*)(Idx4_g + g * 16);
        int4 i0 = Ip[0], i1 = Ip[1], i2 = Ip[2], i3 = Ip[3];

        ull x2[16];
        x2[0]  = gpk(ob, i0.x); x2[1]  = gpk(ob, i0.y);
        x2[2]  = gpk(ob, i0.z); x2[3]  = gpk(ob, i0.w);
        x2[4]  = gpk(ob, i1.x); x2[5]  = gpk(ob, i1.y);
        x2[6]  = gpk(ob, i1.z); x2[7]  = gpk(ob, i1.w);
        x2[8]  = gpk(ob, i2.x); x2[9]  = gpk(ob, i2.y);
        x2[10] = gpk(ob, i2.z); x2[11] = gpk(ob, i2.w);
        x2[12] = gpk(ob, i3.x); x2[13] = gpk(ob, i3.y);
        x2[14] = gpk(ob, i3.z); x2[15] = gpk(ob, i3.w);

        /* hidden: 4 h-pairs, 16 inputs each (weights pre-interleaved) */
        const ulonglong2* Wp = (const ulonglong2*)(Wpk_g + (size_t)g * 128);
        ull f2[8];
        #pragma unroll
        for (int p = 0; p < 4; ++p) {
            ull s = 0ull;
            #pragma unroll
            for (int k = 0; k < 8; ++k) {
                ulonglong2 wv = Wp[p * 8 + k];
                ffma2(s, wv.x, x2[2 * k]);
                ffma2(s, wv.y, x2[2 * k + 1]);
            }
            float2 v = unpack2(s);
            float fa = fmaxf(v.x, 0.f), fb = fmaxf(v.y, 0.f);
            f2[2 * p]     = pack2(fa, fa);
            f2[2 * p + 1] = pack2(fb, fb);
        }

        /* Q head: 9 action-pairs x 8 hidden (weights pre-interleaved) */
        const ulonglong2* Qp = (const ulonglong2*)(Qpk_g + (size_t)g * 144);
        #pragma unroll
        for (int a2 = 0; a2 < 9; ++a2) {
            ulonglong2 qa = Qp[a2 * 4 + 0];
            ulonglong2 qb = Qp[a2 * 4 + 1];
            ulonglong2 qc = Qp[a2 * 4 + 2];
            ulonglong2 qd = Qp[a2 * 4 + 3];
            ffma2(acc2[a2], qa.x, f2[0]); ffma2(acc2[a2], qa.y, f2[1]);
            ffma2(acc2[a2], qb.x, f2[2]); ffma2(acc2[a2], qb.y, f2[3]);
            ffma2(acc2[a2], qc.x, f2[4]); ffma2(acc2[a2], qc.y, f2[5]);
            ffma2(acc2[a2], qd.x, f2[6]); ffma2(acc2[a2], qd.y, f2[7]);
        }
    }

    /* combine parities (deterministic), store per-warp partials */
    #pragma unroll
    for (int a2 = 0; a2 < 9; ++a2) {
        ull o = __shfl_xor_sync(0xffffffffu, acc2[a2], 1);
        acc2[a2] = addf2(acc2[a2], o);
    }
    if (gpar == 0) {
        ull* P = (ull*)(smf + P_OFF) + (w * ROWS + row) * 9;
        #pragma unroll
        for (int a2 = 0; a2 < 9; ++a2) P[a2] = acc2[a2];
    }

    /* obs-direct Q part: warp w handles row w, fp32 obs from gmem, packed qW */
    {
        ull oacc[9];
        #pragma unroll
        for (int a2 = 0; a2 < 9; ++a2) oacc[a2] = 0ull;
        const float* orow = obs + (size_t)(r0 + w) * OBS_DIMV;
        #pragma unroll 2
        for (int st = 0; st < 64; ++st) {
            int j0 = st * 64 + lane * 2;
            float2 ov = *(const float2*)(orow + j0);
            ull oA = pack2(ov.x, ov.x);
            ull oB = pack2(ov.y, ov.y);
            #pragma unroll
            for (int a2 = 0; a2 < 9; ++a2) {
                ulonglong2 qv = *(const ulonglong2*)(Qobs_g + a2 * 8192 + j0 * 2);
                ffma2(oacc[a2], qv.x, oA);
                ffma2(oacc[a2], qv.y, oB);
            }
        }
        #pragma unroll
        for (int a2 = 0; a2 < 9; ++a2) {
            #pragma unroll
            for (int off = 16; off >= 1; off >>= 1) {
                ull o = __shfl_xor_sync(0xffffffffu, oacc[a2], off);
                oacc[a2] = addf2(oacc[a2], o);
            }
        }
        if (lane == 0) {
            ull* Po = (ull*)(smf + POBS_OFF) + w * 9;
            #pragma unroll
            for (int a2 = 0; a2 < 9; ++a2) Po[a2] = oacc[a2];
        }
    }
    __syncthreads();

    /* final reduction: 144 threads, each sums 16 gvf partials + 1 obs partial */
    if (tid < ROWS * 9) {
        int rr = tid / 9;
        int a2 = tid - rr * 9;
        float sx = 0.f, sy = 0.f;
        const ull* P = (const ull*)(smf + P_OFF);
        #pragma unroll
        for (int p = 0; p < NWARP; ++p) {
            float2 v = unpack2(P[(p * ROWS + rr) * 9 + a2]);
            sx += v.x; sy += v.y;
        }
        float2 vo = unpack2(((const ull*)(smf + POBS_OFF))[rr * 9 + a2]);
        sx += vo.x; sy += vo.y;
        out[(size_t)(r0 + rr) * NA + 2 * a2]     = sx;
        out[(size_t)(r0 + rr) * NA + 2 * a2 + 1] = sy;
    }
}

extern "C" void kernel_launch(void* const* d_in, const int* in_sizes, int n_in,
                              void* d_out, int out_size)
{
    const float* obs  = (const float*)d_in[0];
    const float* gvfW = (const float*)d_in[1];
    const float* qW   = (const float*)d_in[2];
    const int*   gidx = (const int*)d_in[3];
    float* out = (float*)d_out;

    repack_kernel<<<(N_TOT + 255) / 256, 256>>>(gvfW, qW, gidx);

    cudaFuncSetAttribute(nibbler_main,
                         cudaFuncAttributeMaxDynamicSharedMemorySize, SMEM_BYTES);
    nibbler_main<<<2048 / ROWS, THREADS, SMEM_BYTES>>>(obs, out);
}

// round 5
// speedup vs baseline: 1.9786x; 1.9786x over previous
#include <cuda_runtime.h>
#include <cuda_fp16.h>
#include <cstdint>

typedef unsigned long long ull;

#define OBS_DIMV 4096
#define NGVF     4096
#define NA       18
#define ROWS     16
#define THREADS  512
#define NWARP    16
#define PAIRS    8
#define CHUNK    32
#define NCHUNK   128
#define OSTRIDE_H2 4100

/* smem strides (floats), all 16B-aligned */
#define WSTRIDE  132
#define QSTRIDE  148
#define ISTRIDE  20

/* float offsets in dynamic smem */
#define OBS_FLOATS (PAIRS * OSTRIDE_H2)        /* 32800 */
#define W_OFF    OBS_FLOATS                    /* 32800 */
#define W_SZ     (CHUNK * WSTRIDE)             /* 4224  */
#define Q_OFF    (W_OFF + 2 * W_SZ)            /* 41248 */
#define Q_SZ     (CHUNK * QSTRIDE)             /* 4736  */
#define I_OFF    (Q_OFF + 2 * Q_SZ)            /* 50720 */
#define I_SZ     (CHUNK * ISTRIDE)             /* 640   */
#define P_OFF    (I_OFF + 2 * I_SZ)            /* 52000 */
#define P_FLOATS (NWARP * ROWS * 9 * 2)        /* 4608  */
#define POBS_OFF (P_OFF + P_FLOATS)            /* 56608 */
#define POBS_FLOATS (NWARP * 9 * 2)            /* 288   */
#define SMEM_FLOATS (POBS_OFF + POBS_FLOATS)   /* 56896 */
#define SMEM_BYTES  (SMEM_FLOATS * 4)          /* 227584 <= 232448 */

/* obs-direct qW slice staging reuses [W_OFF, P_OFF) = 19200 floats */
#define QO_SLICE_COLS 1024
#define QO_SLICE_FLOATS (9 * QO_SLICE_COLS * 2)   /* 18432 <= 19200 */

/* ---- repacked weights in device scratch (rebuilt every launch) ---- */
__device__ float Wpk_g[(size_t)NGVF * 128];   /* [g][hpair][input][2]  */
__device__ float Qpk_g[(size_t)NGVF * 144];   /* [g][a2][h][2]         */
__device__ float Qobs_g[9 * OBS_DIMV * 2];    /* [a2][j][2]            */
__device__ int   Idx4_g[NGVF * 16];           /* gather byte offsets   */

#define N_W  524288
#define N_Q  589824
#define N_QO 73728
#define N_I  65536
#define N_TOT (N_W + N_Q + N_QO + N_I)

__global__ void repack_kernel(const float* __restrict__ gvfW,
                              const float* __restrict__ qW,
                              const int*   __restrict__ gidx)
{
    int id = blockIdx.x * 256 + threadIdx.x;
    if (id < N_W) {
        int g = id >> 7, r = id & 127;
        int p = r >> 5, q = r & 31, i = q >> 1, s = q & 1;
        Wpk_g[id] = gvfW[g * 128 + (2 * p + s) * 16 + i];
    } else if (id < N_W + N_Q) {
        int t = id - N_W;
        int g = t / 144, r = t - g * 144;
        int a2 = r >> 4, q = r & 15, h = q >> 1, s = q & 1;
        Qpk_g[t] = qW[(size_t)(2 * a2 + s) * (OBS_DIMV + NGVF * 8)
                      + OBS_DIMV + (size_t)g * 8 + h];
    } else if (id < N_W + N_Q + N_QO) {
        int t = id - (N_W + N_Q);
        int a2 = t >> 13, r = t & 8191, j = r >> 1, s = r & 1;
        Qobs_g[t] = qW[(size_t)(2 * a2 + s) * (OBS_DIMV + NGVF * 8) + j];
    } else if (id < N_TOT) {
        int t = id - (N_W + N_Q + N_QO);
        Idx4_g[t] = gidx[t] * 4;
    }
}

/* ---- helpers ---- */
__device__ __forceinline__ void cp16(uint32_t dst, const void* src) {
    asm volatile("cp.async.cg.shared.global [%0], [%1], 16;\n" :: "r"(dst), "l"(src));
}
__device__ __forceinline__ void cp_commit() { asm volatile("cp.async.commit_group;\n"); }
template <int N>
__device__ __forceinline__ void cp_wait() { asm volatile("cp.async.wait_group %0;\n" :: "n"(N)); }

__device__ __forceinline__ ull pack2(float a, float b) {
    ull r; asm("mov.b64 %0,{%1,%2};" : "=l"(r) : "f"(a), "f"(b)); return r;
}
__device__ __forceinline__ float2 unpack2(ull v) {
    float2 f; asm("mov.b64 {%0,%1},%2;" : "=f"(f.x), "=f"(f.y) : "l"(v)); return f;
}
__device__ __forceinline__ void ffma2(ull& d, ull a, ull b) {
    asm("fma.rn.f32x2 %0,%1,%2,%0;" : "+l"(d) : "l"(a), "l"(b));
}
__device__ __forceinline__ ull addf2(ull a, ull b) {
    ull r; asm("add.rn.f32x2 %0,%1,%2;" : "=l"(r) : "l"(a), "l"(b)); return r;
}
__device__ __forceinline__ ull gpk(const char* ob, int off) {
    float v = __half2float(*(const __half*)(ob + off));
    return pack2(v, v);
}

__device__ __forceinline__ void stage_chunk(int c, int buf, uint32_t sbase, int tid)
{
    uint32_t wdst = sbase + (uint32_t)(W_OFF + buf * W_SZ) * 4u;
    uint32_t qdst = sbase + (uint32_t)(Q_OFF + buf * Q_SZ) * 4u;
    uint32_t idst = sbase + (uint32_t)(I_OFF + buf * I_SZ) * 4u;
    const float* wsrc = Wpk_g + (size_t)c * CHUNK * 128;
    const float* qsrc = Qpk_g + (size_t)c * CHUNK * 144;
    const int*   isrc = Idx4_g + c * CHUNK * 16;

    /* Wpk chunk: 1024 cp16 */
    #pragma unroll
    for (int k = 0; k < 2; ++k) {
        int id = tid + k * THREADS;
        int g = id >> 5, j = id & 31;
        cp16(wdst + (uint32_t)(g * WSTRIDE + j * 4) * 4u, wsrc + g * 128 + j * 4);
    }
    /* idx chunk: 128 cp16 */
    if (tid < 128) {
        int g = tid >> 2, j = tid & 3;
        cp16(idst + (uint32_t)(g * ISTRIDE + j * 4) * 4u, isrc + g * 16 + j * 4);
    }
    /* Qpk chunk: 1152 cp16 */
    #pragma unroll
    for (int k = 0; k < 3; ++k) {
        int id = tid + k * THREADS;
        if (id < 1152) {
            int g = id / 36, r = id - g * 36;
            cp16(qdst + (uint32_t)(g * QSTRIDE + r * 4) * 4u, qsrc + g * 144 + r * 4);
        }
    }
}

extern __shared__ float smf[];

__global__ void __launch_bounds__(THREADS, 1)
nibbler_main(const float* __restrict__ obs, float* __restrict__ out)
{
    const int tid  = threadIdx.x;
    const int w    = tid >> 5;
    const int lane = tid & 31;
    const int gpar = lane & 1;      /* gvf parity within warp */
    const int row  = lane >> 1;     /* batch row 0..15        */
    const int pair = row >> 1;
    const int rh   = row & 1;
    const int r0   = blockIdx.x * ROWS;

    uint32_t sbase = (uint32_t)__cvta_generic_to_shared(smf);

    stage_chunk(0, 0, sbase, tid);
    cp_commit();

    /* stage 16 obs rows into smem as fp16 half2 row-pairs */
    {
        __half2* sObs = reinterpret_cast<__half2*>(smf);
        #pragma unroll 4
        for (int id = tid; id < PAIRS * (OBS_DIMV / 4); id += THREADS) {
            int p = id >> 10, j = id & 1023;
            float4 va = *(const float4*)(obs + (size_t)(r0 + 2 * p    ) * OBS_DIMV + j * 4);
            float4 vb = *(const float4*)(obs + (size_t)(r0 + 2 * p + 1) * OBS_DIMV + j * 4);
            __half2 h0 = __floats2half2_rn(va.x, vb.x);
            __half2 h1 = __floats2half2_rn(va.y, vb.y);
            __half2 h2 = __floats2half2_rn(va.z, vb.z);
            __half2 h3 = __floats2half2_rn(va.w, vb.w);
            uint4 pk;
            pk.x = *reinterpret_cast<uint32_t*>(&h0);
            pk.y = *reinterpret_cast<uint32_t*>(&h1);
            pk.z = *reinterpret_cast<uint32_t*>(&h2);
            pk.w = *reinterpret_cast<uint32_t*>(&h3);
            *(uint4*)(sObs + p * OSTRIDE_H2 + j * 4) = pk;
        }
    }

    const char* ob = (const char*)smf + pair * (OSTRIDE_H2 * 4) + rh * 2;
    const int gl = w * 2 + gpar;   /* gvf index within chunk */

    ull acc2[9];
    #pragma unroll
    for (int a = 0; a < 9; ++a) acc2[a] = 0ull;

    #pragma unroll 1
    for (int c = 0; c < NCHUNK; ++c) {
        if (c + 1 < NCHUNK) {
            stage_chunk(c + 1, (c + 1) & 1, sbase, tid);
            cp_commit();
            cp_wait<1>();
        } else {
            cp_wait<0>();
        }
        __syncthreads();

        const int buf = c & 1;
        const ulonglong2* Wp = (const ulonglong2*)(smf + W_OFF + buf * W_SZ + gl * WSTRIDE);
        const ulonglong2* Qp = (const ulonglong2*)(smf + Q_OFF + buf * Q_SZ + gl * QSTRIDE);
        const int4*       I4 = (const int4*)((const int*)(smf + I_OFF + buf * I_SZ) + gl * ISTRIDE);

        int4 i0 = I4[0], i1 = I4[1], i2 = I4[2], i3 = I4[3];
        ull x2[16];
        x2[0]  = gpk(ob, i0.x); x2[1]  = gpk(ob, i0.y);
        x2[2]  = gpk(ob, i0.z); x2[3]  = gpk(ob, i0.w);
        x2[4]  = gpk(ob, i1.x); x2[5]  = gpk(ob, i1.y);
        x2[6]  = gpk(ob, i1.z); x2[7]  = gpk(ob, i1.w);
        x2[8]  = gpk(ob, i2.x); x2[9]  = gpk(ob, i2.y);
        x2[10] = gpk(ob, i2.z); x2[11] = gpk(ob, i2.w);
        x2[12] = gpk(ob, i3.x); x2[13] = gpk(ob, i3.y);
        x2[14] = gpk(ob, i3.z); x2[15] = gpk(ob, i3.w);

        /* hidden: 4 h-pairs x 16 inputs (pre-interleaved), ReLU */
        ull f2[8];
        #pragma unroll
        for (int p = 0; p < 4; ++p) {
            ull s = 0ull;
            #pragma unroll
            for (int k = 0; k < 8; ++k) {
                ulonglong2 wv = Wp[p * 8 + k];
                ffma2(s, wv.x, x2[2 * k]);
                ffma2(s, wv.y, x2[2 * k + 1]);
            }
            float2 v = unpack2(s);
            float fa = fmaxf(v.x, 0.f), fb = fmaxf(v.y, 0.f);
            f2[2 * p]     = pack2(fa, fa);
            f2[2 * p + 1] = pack2(fb, fb);
        }

        /* Q head: 9 action-pairs x 8 hidden */
        #pragma unroll
        for (int a2 = 0; a2 < 9; ++a2) {
            ulonglong2 qa = Qp[a2 * 4 + 0];
            ulonglong2 qb = Qp[a2 * 4 + 1];
            ulonglong2 qc = Qp[a2 * 4 + 2];
            ulonglong2 qd = Qp[a2 * 4 + 3];
            ffma2(acc2[a2], qa.x, f2[0]); ffma2(acc2[a2], qa.y, f2[1]);
            ffma2(acc2[a2], qb.x, f2[2]); ffma2(acc2[a2], qb.y, f2[3]);
            ffma2(acc2[a2], qc.x, f2[4]); ffma2(acc2[a2], qc.y, f2[5]);
            ffma2(acc2[a2], qd.x, f2[6]); ffma2(acc2[a2], qd.y, f2[7]);
        }
        __syncthreads();
    }

    /* combine the 2 gvf parities per row (deterministic) */
    #pragma unroll
    for (int a2 = 0; a2 < 9; ++a2) {
        ull o = __shfl_xor_sync(0xffffffffu, acc2[a2], 1);
        acc2[a2] = addf2(acc2[a2], o);
    }
    if (gpar == 0) {
        ull* P = (ull*)(smf + P_OFF) + (w * ROWS + row) * 9;
        #pragma unroll
        for (int a2 = 0; a2 < 9; ++a2) P[a2] = acc2[a2];
    }
    __syncthreads();   /* weight buffers now free for qW-slice staging */

    /* ---- obs-direct Q part, smem-staged qW slices (read once per CTA) ----
       warp w owns batch row w; lanes split columns j = s*1024 + jj*64 + lane*2 */
    {
        ull oacc[9];
        #pragma unroll
        for (int a2 = 0; a2 < 9; ++a2) oacc[a2] = 0ull;
        const float* orow = obs + (size_t)(r0 + w) * OBS_DIMV;

        #pragma unroll 1
        for (int s = 0; s < OBS_DIMV / QO_SLICE_COLS; ++s) {
            /* stage Qobs slice [9][1024][2] into smem at W_OFF (4608 cp16) */
            #pragma unroll
            for (int k = 0; k < 9; ++k) {
                int id = tid + k * THREADS;   /* 0..4607 */
                int a2 = id >> 9;             /* /512    */
                int t  = id & 511;
                cp16(sbase + (uint32_t)(W_OFF + a2 * 2048 + t * 4) * 4u,
                     Qobs_g + a2 * (OBS_DIMV * 2) + s * (QO_SLICE_COLS * 2) + t * 4);
            }
            cp_commit();
            cp_wait<0>();
            __syncthreads();

            #pragma unroll 2
            for (int jj = 0; jj < 16; ++jj) {
                int jloc = jj * 64 + lane * 2;            /* col within slice */
                float2 ov = *(const float2*)(orow + s * QO_SLICE_COLS + jloc);
                ull oA = pack2(ov.x, ov.x);
                ull oB = pack2(ov.y, ov.y);
                #pragma unroll
                for (int a2 = 0; a2 < 9; ++a2) {
                    ulonglong2 qv = *(const ulonglong2*)(smf + W_OFF + a2 * 2048 + jloc * 2);
                    ffma2(oacc[a2], qv.x, oA);
                    ffma2(oacc[a2], qv.y, oB);
                }
            }
            __syncthreads();
        }

        #pragma unroll
        for (int a2 = 0; a2 < 9; ++a2) {
            #pragma unroll
            for (int off = 16; off >= 1; off >>= 1) {
                ull o = __shfl_xor_sync(0xffffffffu, oacc[a2], off);
                oacc[a2] = addf2(oacc[a2], o);
            }
        }
        if (lane == 0) {
            ull* Po = (ull*)(smf + POBS_OFF) + w * 9;
            #pragma unroll
            for (int a2 = 0; a2 < 9; ++a2) Po[a2] = oacc[a2];
        }
    }
    __syncthreads();

    /* final: 144 threads sum 16 gvf partials + 1 obs partial */
    if (tid < ROWS * 9) {
        int rr = tid / 9;
        int a2 = tid - rr * 9;
        float sx = 0.f, sy = 0.f;
        const ull* P = (const ull*)(smf + P_OFF);
        #pragma unroll
        for (int p = 0; p < NWARP; ++p) {
            float2 v = unpack2(P[(p * ROWS + rr) * 9 + a2]);
            sx += v.x; sy += v.y;
        }
        float2 vo = unpack2(((const ull*)(smf + POBS_OFF))[rr * 9 + a2]);
        sx += vo.x; sy += vo.y;
        out[(size_t)(r0 + rr) * NA + 2 * a2]     = sx;
        out[(size_t)(r0 + rr) * NA + 2 * a2 + 1] = sy;
    }
}

extern "C" void kernel_launch(void* const* d_in, const int* in_sizes, int n_in,
                              void* d_out, int out_size)
{
    const float* obs  = (const float*)d_in[0];
    const float* gvfW = (const float*)d_in[1];
    const float* qW   = (const float*)d_in[2];
    const int*   gidx = (const int*)d_in[3];
    float* out = (float*)d_out;

    repack_kernel<<<(N_TOT + 255) / 256, 256>>>(gvfW, qW, gidx);

    cudaFuncSetAttribute(nibbler_main,
                         cudaFuncAttributeMaxDynamicSharedMemorySize, SMEM_BYTES);
    nibbler_main<<<2048 / ROWS, THREADS, SMEM_BYTES>>>(obs, out);
}

// round 6
// speedup vs baseline: 1.9788x; 1.0001x over previous
#include <cuda_runtime.h>
#include <cuda_fp16.h>
#include <cstdint>

typedef unsigned long long ull;

#define OBS_DIMV 4096
#define NGVF     4096
#define NA       18
#define ROWS     16
#define THREADS  512
#define NWARP    16
#define PAIRS    8
#define CHUNK    32
#define NCHUNK   128
#define OSTRIDE_H2 4100

/* smem strides (floats), all 16B-aligned */
#define WSTRIDE  132
#define QSTRIDE  148
#define ISTRIDE  20

/* float offsets in dynamic smem */
#define OBS_FLOATS (PAIRS * OSTRIDE_H2)        /* 32800 */
#define W_OFF    OBS_FLOATS                    /* 32800 */
#define W_SZ     (CHUNK * WSTRIDE)             /* 4224  */
#define Q_OFF    (W_OFF + 2 * W_SZ)            /* 41248 */
#define Q_SZ     (CHUNK * QSTRIDE)             /* 4736  */
#define I_OFF    (Q_OFF + 2 * Q_SZ)            /* 50720 */
#define I_SZ     (CHUNK * ISTRIDE)             /* 640   */
#define P_OFF    (I_OFF + 2 * I_SZ)            /* 52000 */
#define P_FLOATS (NWARP * ROWS * 9 * 2)        /* 4608  */
#define POBS_OFF (P_OFF + P_FLOATS)            /* 56608 */
#define POBS_FLOATS (NWARP * 9 * 2)            /* 288   */
#define SMEM_FLOATS (POBS_OFF + POBS_FLOATS)   /* 56896 */
#define SMEM_BYTES  (SMEM_FLOATS * 4)          /* 227584 <= 232448 */

/* obs-direct qW slice staging reuses [W_OFF, P_OFF) = 19200 floats */
#define QO_SLICE_COLS 1024
#define QO_SLICE_FLOATS (9 * QO_SLICE_COLS * 2)   /* 18432 <= 19200 */

/* ---- repacked weights in device scratch (rebuilt every launch) ---- */
__device__ float Wpk_g[(size_t)NGVF * 128];   /* [g][hpair][input][2]  */
__device__ float Qpk_g[(size_t)NGVF * 144];   /* [g][a2][h][2]         */
__device__ float Qobs_g[9 * OBS_DIMV * 2];    /* [a2][j][2]            */
__device__ int   Idx4_g[NGVF * 16];           /* gather byte offsets   */

#define N_W  524288
#define N_Q  589824
#define N_QO 73728
#define N_I  65536
#define N_TOT (N_W + N_Q + N_QO + N_I)

__global__ void repack_kernel(const float* __restrict__ gvfW,
                              const float* __restrict__ qW,
                              const int*   __restrict__ gidx)
{
    int id = blockIdx.x * 256 + threadIdx.x;
    if (id < N_W) {
        int g = id >> 7, r = id & 127;
        int p = r >> 5, q = r & 31, i = q >> 1, s = q & 1;
        Wpk_g[id] = gvfW[g * 128 + (2 * p + s) * 16 + i];
    } else if (id < N_W + N_Q) {
        int t = id - N_W;
        int g = t / 144, r = t - g * 144;
        int a2 = r >> 4, q = r & 15, h = q >> 1, s = q & 1;
        Qpk_g[t] = qW[(size_t)(2 * a2 + s) * (OBS_DIMV + NGVF * 8)
                      + OBS_DIMV + (size_t)g * 8 + h];
    } else if (id < N_W + N_Q + N_QO) {
        int t = id - (N_W + N_Q);
        int a2 = t >> 13, r = t & 8191, j = r >> 1, s = r & 1;
        Qobs_g[t] = qW[(size_t)(2 * a2 + s) * (OBS_DIMV + NGVF * 8) + j];
    } else if (id < N_TOT) {
        int t = id - (N_W + N_Q + N_QO);
        Idx4_g[t] = gidx[t] * 4;
    }
}

/* ---- helpers ---- */
__device__ __forceinline__ void cp16(uint32_t dst, const void* src) {
    asm volatile("cp.async.cg.shared.global [%0], [%1], 16;\n" :: "r"(dst), "l"(src));
}
__device__ __forceinline__ void cp_commit() { asm volatile("cp.async.commit_group;\n"); }
template <int N>
__device__ __forceinline__ void cp_wait() { asm volatile("cp.async.wait_group %0;\n" :: "n"(N)); }

__device__ __forceinline__ ull pack2(float a, float b) {
    ull r; asm("mov.b64 %0,{%1,%2};" : "=l"(r) : "f"(a), "f"(b)); return r;
}
__device__ __forceinline__ float2 unpack2(ull v) {
    float2 f; asm("mov.b64 {%0,%1},%2;" : "=f"(f.x), "=f"(f.y) : "l"(v)); return f;
}
__device__ __forceinline__ void ffma2(ull& d, ull a, ull b) {
    asm("fma.rn.f32x2 %0,%1,%2,%0;" : "+l"(d) : "l"(a), "l"(b));
}
__device__ __forceinline__ ull addf2(ull a, ull b) {
    ull r; asm("add.rn.f32x2 %0,%1,%2;" : "=l"(r) : "l"(a), "l"(b)); return r;
}
__device__ __forceinline__ ull gpk(const char* ob, int off) {
    float v = __half2float(*(const __half*)(ob + off));
    return pack2(v, v);
}

__device__ __forceinline__ void stage_chunk(int c, int buf, uint32_t sbase, int tid)
{
    uint32_t wdst = sbase + (uint32_t)(W_OFF + buf * W_SZ) * 4u;
    uint32_t qdst = sbase + (uint32_t)(Q_OFF + buf * Q_SZ) * 4u;
    uint32_t idst = sbase + (uint32_t)(I_OFF + buf * I_SZ) * 4u;
    const float* wsrc = Wpk_g + (size_t)c * CHUNK * 128;
    const float* qsrc = Qpk_g + (size_t)c * CHUNK * 144;
    const int*   isrc = Idx4_g + c * CHUNK * 16;

    /* Wpk chunk: 1024 cp16 */
    #pragma unroll
    for (int k = 0; k < 2; ++k) {
        int id = tid + k * THREADS;
        int g = id >> 5, j = id & 31;
        cp16(wdst + (uint32_t)(g * WSTRIDE + j * 4) * 4u, wsrc + g * 128 + j * 4);
    }
    /* idx chunk: 128 cp16 */
    if (tid < 128) {
        int g = tid >> 2, j = tid & 3;
        cp16(idst + (uint32_t)(g * ISTRIDE + j * 4) * 4u, isrc + g * 16 + j * 4);
    }
    /* Qpk chunk: 1152 cp16 */
    #pragma unroll
    for (int k = 0; k < 3; ++k) {
        int id = tid + k * THREADS;
        if (id < 1152) {
            int g = id / 36, r = id - g * 36;
            cp16(qdst + (uint32_t)(g * QSTRIDE + r * 4) * 4u, qsrc + g * 144 + r * 4);
        }
    }
}

extern __shared__ float smf[];

__global__ void __launch_bounds__(THREADS, 1)
nibbler_main(const float* __restrict__ obs, float* __restrict__ out)
{
    const int tid  = threadIdx.x;
    const int w    = tid >> 5;
    const int lane = tid & 31;
    const int gpar = lane & 1;      /* gvf parity within warp */
    const int row  = lane >> 1;     /* batch row 0..15        */
    const int pair = row >> 1;
    const int rh   = row & 1;
    const int r0   = blockIdx.x * ROWS;

    uint32_t sbase = (uint32_t)__cvta_generic_to_shared(smf);

    stage_chunk(0, 0, sbase, tid);
    cp_commit();

    /* stage 16 obs rows into smem as fp16 half2 row-pairs */
    {
        __half2* sObs = reinterpret_cast<__half2*>(smf);
        #pragma unroll 4
        for (int id = tid; id < PAIRS * (OBS_DIMV / 4); id += THREADS) {
            int p = id >> 10, j = id & 1023;
            float4 va = *(const float4*)(obs + (size_t)(r0 + 2 * p    ) * OBS_DIMV + j * 4);
            float4 vb = *(const float4*)(obs + (size_t)(r0 + 2 * p + 1) * OBS_DIMV + j * 4);
            __half2 h0 = __floats2half2_rn(va.x, vb.x);
            __half2 h1 = __floats2half2_rn(va.y, vb.y);
            __half2 h2 = __floats2half2_rn(va.z, vb.z);
            __half2 h3 = __floats2half2_rn(va.w, vb.w);
            uint4 pk;
            pk.x = *reinterpret_cast<uint32_t*>(&h0);
            pk.y = *reinterpret_cast<uint32_t*>(&h1);
            pk.z = *reinterpret_cast<uint32_t*>(&h2);
            pk.w = *reinterpret_cast<uint32_t*>(&h3);
            *(uint4*)(sObs + p * OSTRIDE_H2 + j * 4) = pk;
        }
    }

    const char* ob = (const char*)smf + pair * (OSTRIDE_H2 * 4) + rh * 2;
    const int gl = w * 2 + gpar;   /* gvf index within chunk */

    ull acc2[9];
    #pragma unroll
    for (int a = 0; a < 9; ++a) acc2[a] = 0ull;

    #pragma unroll 1
    for (int c = 0; c < NCHUNK; ++c) {
        if (c + 1 < NCHUNK) {
            stage_chunk(c + 1, (c + 1) & 1, sbase, tid);
            cp_commit();
            cp_wait<1>();
        } else {
            cp_wait<0>();
        }
        __syncthreads();

        const int buf = c & 1;
        const ulonglong2* Wp = (const ulonglong2*)(smf + W_OFF + buf * W_SZ + gl * WSTRIDE);
        const ulonglong2* Qp = (const ulonglong2*)(smf + Q_OFF + buf * Q_SZ + gl * QSTRIDE);
        const int4*       I4 = (const int4*)((const int*)(smf + I_OFF + buf * I_SZ) + gl * ISTRIDE);

        int4 i0 = I4[0], i1 = I4[1], i2 = I4[2], i3 = I4[3];
        ull x2[16];
        x2[0]  = gpk(ob, i0.x); x2[1]  = gpk(ob, i0.y);
        x2[2]  = gpk(ob, i0.z); x2[3]  = gpk(ob, i0.w);
        x2[4]  = gpk(ob, i1.x); x2[5]  = gpk(ob, i1.y);
        x2[6]  = gpk(ob, i1.z); x2[7]  = gpk(ob, i1.w);
        x2[8]  = gpk(ob, i2.x); x2[9]  = gpk(ob, i2.y);
        x2[10] = gpk(ob, i2.z); x2[11] = gpk(ob, i2.w);
        x2[12] = gpk(ob, i3.x); x2[13] = gpk(ob, i3.y);
        x2[14] = gpk(ob, i3.z); x2[15] = gpk(ob, i3.w);

        /* hidden: 4 h-pairs x 16 inputs (pre-interleaved), ReLU */
        ull f2[8];
        #pragma unroll
        for (int p = 0; p < 4; ++p) {
            ull s = 0ull;
            #pragma unroll
            for (int k = 0; k < 8; ++k) {
                ulonglong2 wv = Wp[p * 8 + k];
                ffma2(s, wv.x, x2[2 * k]);
                ffma2(s, wv.y, x2[2 * k + 1]);
            }
            float2 v = unpack2(s);
            float fa = fmaxf(v.x, 0.f), fb = fmaxf(v.y, 0.f);
            f2[2 * p]     = pack2(fa, fa);
            f2[2 * p + 1] = pack2(fb, fb);
        }

        /* Q head: 9 action-pairs x 8 hidden */
        #pragma unroll
        for (int a2 = 0; a2 < 9; ++a2) {
            ulonglong2 qa = Qp[a2 * 4 + 0];
            ulonglong2 qb = Qp[a2 * 4 + 1];
            ulonglong2 qc = Qp[a2 * 4 + 2];
            ulonglong2 qd = Qp[a2 * 4 + 3];
            ffma2(acc2[a2], qa.x, f2[0]); ffma2(acc2[a2], qa.y, f2[1]);
            ffma2(acc2[a2], qb.x, f2[2]); ffma2(acc2[a2], qb.y, f2[3]);
            ffma2(acc2[a2], qc.x, f2[4]); ffma2(acc2[a2], qc.y, f2[5]);
            ffma2(acc2[a2], qd.x, f2[6]); ffma2(acc2[a2], qd.y, f2[7]);
        }
        __syncthreads();
    }

    /* combine the 2 gvf parities per row (deterministic) */
    #pragma unroll
    for (int a2 = 0; a2 < 9; ++a2) {
        ull o = __shfl_xor_sync(0xffffffffu, acc2[a2], 1);
        acc2[a2] = addf2(acc2[a2], o);
    }
    if (gpar == 0) {
        ull* P = (ull*)(smf + P_OFF) + (w * ROWS + row) * 9;
        #pragma unroll
        for (int a2 = 0; a2 < 9; ++a2) P[a2] = acc2[a2];
    }
    __syncthreads();   /* weight buffers now free for qW-slice staging */

    /* ---- obs-direct Q part, smem-staged qW slices (read once per CTA) ----
       warp w owns batch row w; lanes split columns j = s*1024 + jj*64 + lane*2 */
    {
        ull oacc[9];
        #pragma unroll
        for (int a2 = 0; a2 < 9; ++a2) oacc[a2] = 0ull;
        const float* orow = obs + (size_t)(r0 + w) * OBS_DIMV;

        #pragma unroll 1
        for (int s = 0; s < OBS_DIMV / QO_SLICE_COLS; ++s) {
            /* stage Qobs slice [9][1024][2] into smem at W_OFF (4608 cp16) */
            #pragma unroll
            for (int k = 0; k < 9; ++k) {
                int id = tid + k * THREADS;   /* 0..4607 */
                int a2 = id >> 9;             /* /512    */
                int t  = id & 511;
                cp16(sbase + (uint32_t)(W_OFF + a2 * 2048 + t * 4) * 4u,
                     Qobs_g + a2 * (OBS_DIMV * 2) + s * (QO_SLICE_COLS * 2) + t * 4);
            }
            cp_commit();
            cp_wait<0>();
            __syncthreads();

            #pragma unroll 2
            for (int jj = 0; jj < 16; ++jj) {
                int jloc = jj * 64 + lane * 2;            /* col within slice */
                float2 ov = *(const float2*)(orow + s * QO_SLICE_COLS + jloc);
                ull oA = pack2(ov.x, ov.x);
                ull oB = pack2(ov.y, ov.y);
                #pragma unroll
                for (int a2 = 0; a2 < 9; ++a2) {
                    ulonglong2 qv = *(const ulonglong2*)(smf + W_OFF + a2 * 2048 + jloc * 2);
                    ffma2(oacc[a2], qv.x, oA);
                    ffma2(oacc[a2], qv.y, oB);
                }
            }
            __syncthreads();
        }

        #pragma unroll
        for (int a2 = 0; a2 < 9; ++a2) {
            #pragma unroll
            for (int off = 16; off >= 1; off >>= 1) {
                ull o = __shfl_xor_sync(0xffffffffu, oacc[a2], off);
                oacc[a2] = addf2(oacc[a2], o);
            }
        }
        if (lane == 0) {
            ull* Po = (ull*)(smf + POBS_OFF) + w * 9;
            #pragma unroll
            for (int a2 = 0; a2 < 9; ++a2) Po[a2] = oacc[a2];
        }
    }
    __syncthreads();

    /* final: 144 threads sum 16 gvf partials + 1 obs partial */
    if (tid < ROWS * 9) {
        int rr = tid / 9;
        int a2 = tid - rr * 9;
        float sx = 0.f, sy = 0.f;
        const ull* P = (const ull*)(smf + P_OFF);
        #pragma unroll
        for (int p = 0; p < NWARP; ++p) {
            float2 v = unpack2(P[(p * ROWS + rr) * 9 + a2]);
            sx += v.x; sy += v.y;
        }
        float2 vo = unpack2(((const ull*)(smf + POBS_OFF))[rr * 9 + a2]);
        sx += vo.x; sy += vo.y;
        out[(size_t)(r0 + rr) * NA + 2 * a2]     = sx;
        out[(size_t)(r0 + rr) * NA + 2 * a2 + 1] = sy;
    }
}

extern "C" void kernel_launch(void* const* d_in, const int* in_sizes, int n_in,
                              void* d_out, int out_size)
{
    const float* obs  = (const float*)d_in[0];
    const float* gvfW = (const float*)d_in[1];
    const float* qW   = (const float*)d_in[2];
    const int*   gidx = (const int*)d_in[3];
    float* out = (float*)d_out;

    repack_kernel<<<(N_TOT + 255) / 256, 256>>>(gvfW, qW, gidx);

    cudaFuncSetAttribute(nibbler_main,
                         cudaFuncAttributeMaxDynamicSharedMemorySize, SMEM_BYTES);
    nibbler_main<<<2048 / ROWS, THREADS, SMEM_BYTES>>>(obs, out);
}

// round 7
// speedup vs baseline: 2.0598x; 1.0409x over previous
#include <cuda_runtime.h>
#include <cuda_fp16.h>
#include <cstdint>

typedef unsigned long long ull;

#define OBS_DIMV 4096
#define NGVF     4096
#define NA       18
#define ROWS     16
#define THREADS  512
#define NWARP    16
#define PAIRS    8
#define CHUNK    32
#define NCHUNK   128
#define OSTRIDE_H2 4100

/* smem strides (floats), all 16B-aligned */
#define WSTRIDE  132
#define QSTRIDE  148
#define ISTRIDE  20

/* float offsets in dynamic smem */
#define OBS_FLOATS (PAIRS * OSTRIDE_H2)        /* 32800 */
#define W_OFF    OBS_FLOATS                    /* 32800 */
#define W_SZ     (CHUNK * WSTRIDE)             /* 4224  */
#define Q_OFF    (W_OFF + 2 * W_SZ)            /* 41248 */
#define Q_SZ     (CHUNK * QSTRIDE)             /* 4736  */
#define I_OFF    (Q_OFF + 2 * Q_SZ)            /* 50720 */
#define I_SZ     (CHUNK * ISTRIDE)             /* 640   */
#define P_OFF    (I_OFF + 2 * I_SZ)            /* 52000 */
#define P_FLOATS (NWARP * ROWS * 9 * 2)        /* 4608  */
#define POBS_OFF (P_OFF + P_FLOATS)            /* 56608 */
#define POBS_FLOATS (NWARP * 9 * 2)            /* 288   */
#define SMEM_FLOATS (POBS_OFF + POBS_FLOATS)   /* 56896 */
#define SMEM_BYTES  (SMEM_FLOATS * 4)          /* 227584 <= 232448 */

/* obs-direct qW tail: two 256-col slice buffers inside the weight region */
#define QO_COLS   256
#define QO_SLICE_FLOATS (9 * QO_COLS * 2)      /* 4608 */
#define NSLICE    (OBS_DIMV / QO_COLS)         /* 16 */

/* ---- repacked weights in device scratch (rebuilt every launch) ---- */
__device__ float Wpk_g[(size_t)NGVF * 128];   /* [g][hpair][input][2]  */
__device__ float Qpk_g[(size_t)NGVF * 144];   /* [g][a2][h][2]         */
__device__ float Qobs_g[9 * OBS_DIMV * 2];    /* [a2][j][2]            */
__device__ int   Idx4_g[NGVF * 16];           /* gather byte offsets   */

#define N_W  524288
#define N_Q  589824
#define N_QO 73728
#define N_I  65536
#define N_TOT (N_W + N_Q + N_QO + N_I)

__global__ void repack_kernel(const float* __restrict__ gvfW,
                              const float* __restrict__ qW,
                              const int*   __restrict__ gidx)
{
    int id = blockIdx.x * 256 + threadIdx.x;
    if (id < N_W) {
        int g = id >> 7, r = id & 127;
        int p = r >> 5, q = r & 31, i = q >> 1, s = q & 1;
        Wpk_g[id] = gvfW[g * 128 + (2 * p + s) * 16 + i];
    } else if (id < N_W + N_Q) {
        int t = id - N_W;
        int g = t / 144, r = t - g * 144;
        int a2 = r >> 4, q = r & 15, h = q >> 1, s = q & 1;
        Qpk_g[t] = qW[(size_t)(2 * a2 + s) * (OBS_DIMV + NGVF * 8)
                      + OBS_DIMV + (size_t)g * 8 + h];
    } else if (id < N_W + N_Q + N_QO) {
        int t = id - (N_W + N_Q);
        int a2 = t >> 13, r = t & 8191, j = r >> 1, s = r & 1;
        Qobs_g[t] = qW[(size_t)(2 * a2 + s) * (OBS_DIMV + NGVF * 8) + j];
    } else if (id < N_TOT) {
        int t = id - (N_W + N_Q + N_QO);
        Idx4_g[t] = gidx[t] * 4;
    }
}

/* ---- helpers ---- */
__device__ __forceinline__ void cp16(uint32_t dst, const void* src) {
    asm volatile("cp.async.cg.shared.global [%0], [%1], 16;\n" :: "r"(dst), "l"(src));
}
__device__ __forceinline__ void cp_commit() { asm volatile("cp.async.commit_group;\n"); }
template <int N>
__device__ __forceinline__ void cp_wait() { asm volatile("cp.async.wait_group %0;\n" :: "n"(N)); }

__device__ __forceinline__ ull pack2(float a, float b) {
    ull r; asm("mov.b64 %0,{%1,%2};" : "=l"(r) : "f"(a), "f"(b)); return r;
}
__device__ __forceinline__ float2 unpack2(ull v) {
    float2 f; asm("mov.b64 {%0,%1},%2;" : "=f"(f.x), "=f"(f.y) : "l"(v)); return f;
}
__device__ __forceinline__ void ffma2(ull& d, ull a, ull b) {
    asm("fma.rn.f32x2 %0,%1,%2,%0;" : "+l"(d) : "l"(a), "l"(b));
}
__device__ __forceinline__ ull addf2(ull a, ull b) {
    ull r; asm("add.rn.f32x2 %0,%1,%2;" : "=l"(r) : "l"(a), "l"(b)); return r;
}
/* dedup'd gather: row-pair lanes load the SAME 32-bit half2 word (broadcast),
   then each extracts its own half via shift+cvt */
__device__ __forceinline__ ull gpk32(const char* obp, int off, int shft) {
    uint32_t v32 = *(const uint32_t*)(obp + off);
    float v = __half2float(__ushort_as_half((unsigned short)(v32 >> shft)));
    return pack2(v, v);
}

__device__ __forceinline__ void stage_chunk(int c, int buf, uint32_t sbase, int tid)
{
    uint32_t wdst = sbase + (uint32_t)(W_OFF + buf * W_SZ) * 4u;
    uint32_t qdst = sbase + (uint32_t)(Q_OFF + buf * Q_SZ) * 4u;
    uint32_t idst = sbase + (uint32_t)(I_OFF + buf * I_SZ) * 4u;
    const float* wsrc = Wpk_g + (size_t)c * CHUNK * 128;
    const float* qsrc = Qpk_g + (size_t)c * CHUNK * 144;
    const int*   isrc = Idx4_g + c * CHUNK * 16;

    #pragma unroll
    for (int k = 0; k < 2; ++k) {
        int id = tid + k * THREADS;
        int g = id >> 5, j = id & 31;
        cp16(wdst + (uint32_t)(g * WSTRIDE + j * 4) * 4u, wsrc + g * 128 + j * 4);
    }
    if (tid < 128) {
        int g = tid >> 2, j = tid & 3;
        cp16(idst + (uint32_t)(g * ISTRIDE + j * 4) * 4u, isrc + g * 16 + j * 4);
    }
    #pragma unroll
    for (int k = 0; k < 3; ++k) {
        int id = tid + k * THREADS;
        if (id < 1152) {
            int g = id / 36, r = id - g * 36;
            cp16(qdst + (uint32_t)(g * QSTRIDE + r * 4) * 4u, qsrc + g * 144 + r * 4);
        }
    }
}

__device__ __forceinline__ void stage_tail(int s, int buf, uint32_t sbase, int tid)
{
    #pragma unroll
    for (int k = 0; k < 3; ++k) {
        int id = tid + k * THREADS;
        if (id < 1152) {
            int a2 = id >> 7, t = id & 127;
            cp16(sbase + (uint32_t)(W_OFF + buf * QO_SLICE_FLOATS + a2 * (QO_COLS * 2) + t * 4) * 4u,
                 Qobs_g + a2 * (OBS_DIMV * 2) + s * (QO_COLS * 2) + t * 4);
        }
    }
}

extern __shared__ float smf[];

__global__ void __launch_bounds__(THREADS, 1)
nibbler_main(const float* __restrict__ obs, float* __restrict__ out)
{
    const int tid  = threadIdx.x;
    const int w    = tid >> 5;
    const int lane = tid & 31;
    const int gpar = lane & 1;      /* gvf parity within warp */
    const int row  = lane >> 1;     /* batch row 0..15        */
    const int pair = row >> 1;
    const int rh   = row & 1;
    const int shft = rh * 16;       /* half-select shift       */
    const int r0   = blockIdx.x * ROWS;

    uint32_t sbase = (uint32_t)__cvta_generic_to_shared(smf);

    stage_chunk(0, 0, sbase, tid);
    cp_commit();

    /* stage 16 obs rows into smem as fp16 half2 row-pairs */
    {
        __half2* sObs = reinterpret_cast<__half2*>(smf);
        #pragma unroll 4
        for (int id = tid; id < PAIRS * (OBS_DIMV / 4); id += THREADS) {
            int p = id >> 10, j = id & 1023;
            float4 va = *(const float4*)(obs + (size_t)(r0 + 2 * p    ) * OBS_DIMV + j * 4);
            float4 vb = *(const float4*)(obs + (size_t)(r0 + 2 * p + 1) * OBS_DIMV + j * 4);
            __half2 h0 = __floats2half2_rn(va.x, vb.x);
            __half2 h1 = __floats2half2_rn(va.y, vb.y);
            __half2 h2 = __floats2half2_rn(va.z, vb.z);
            __half2 h3 = __floats2half2_rn(va.w, vb.w);
            uint4 pk;
            pk.x = *reinterpret_cast<uint32_t*>(&h0);
            pk.y = *reinterpret_cast<uint32_t*>(&h1);
            pk.z = *reinterpret_cast<uint32_t*>(&h2);
            pk.w = *reinterpret_cast<uint32_t*>(&h3);
            *(uint4*)(sObs + p * OSTRIDE_H2 + j * 4) = pk;
        }
    }

    /* pair base (no rh offset: row-pair lanes share the address for dedup) */
    const char* obp = (const char*)smf + pair * (OSTRIDE_H2 * 4);
    const int gl = w * 2 + gpar;

    ull acc2[9];
    #pragma unroll
    for (int a = 0; a < 9; ++a) acc2[a] = 0ull;

    /* ---- main loop: ONE barrier per chunk; stage(c+1) before compute(c) ---- */
    #pragma unroll 1
    for (int c = 0; c < NCHUNK; ++c) {
        cp_wait<0>();
        __syncthreads();
        if (c + 1 < NCHUNK) {
            stage_chunk(c + 1, (c + 1) & 1, sbase, tid);
            cp_commit();
        }

        const int buf = c & 1;
        const ulonglong2* Wp = (const ulonglong2*)(smf + W_OFF + buf * W_SZ + gl * WSTRIDE);
        const ulonglong2* Qp = (const ulonglong2*)(smf + Q_OFF + buf * Q_SZ + gl * QSTRIDE);
        const int4*       I4 = (const int4*)((const int*)(smf + I_OFF + buf * I_SZ) + gl * ISTRIDE);

        int4 i0 = I4[0], i1 = I4[1], i2 = I4[2], i3 = I4[3];
        ull x2[16];
        x2[0]  = gpk32(obp, i0.x, shft); x2[1]  = gpk32(obp, i0.y, shft);
        x2[2]  = gpk32(obp, i0.z, shft); x2[3]  = gpk32(obp, i0.w, shft);
        x2[4]  = gpk32(obp, i1.x, shft); x2[5]  = gpk32(obp, i1.y, shft);
        x2[6]  = gpk32(obp, i1.z, shft); x2[7]  = gpk32(obp, i1.w, shft);
        x2[8]  = gpk32(obp, i2.x, shft); x2[9]  = gpk32(obp, i2.y, shft);
        x2[10] = gpk32(obp, i2.z, shft); x2[11] = gpk32(obp, i2.w, shft);
        x2[12] = gpk32(obp, i3.x, shft); x2[13] = gpk32(obp, i3.y, shft);
        x2[14] = gpk32(obp, i3.z, shft); x2[15] = gpk32(obp, i3.w, shft);

        /* hidden: 4 h-pairs x 16 inputs, two parallel chains, ReLU */
        ull f2[8];
        #pragma unroll
        for (int p = 0; p < 4; ++p) {
            ull s0 = 0ull, s1 = 0ull;
            #pragma unroll
            for (int k = 0; k < 4; ++k) {
                ulonglong2 wva = Wp[p * 8 + k];
                ulonglong2 wvb = Wp[p * 8 + 4 + k];
                ffma2(s0, wva.x, x2[2 * k]);
                ffma2(s0, wva.y, x2[2 * k + 1]);
                ffma2(s1, wvb.x, x2[8 + 2 * k]);
                ffma2(s1, wvb.y, x2[8 + 2 * k + 1]);
            }
            ull s = addf2(s0, s1);
            float2 v = unpack2(s);
            float fa = fmaxf(v.x, 0.f), fb = fmaxf(v.y, 0.f);
            f2[2 * p]     = pack2(fa, fa);
            f2[2 * p + 1] = pack2(fb, fb);
        }

        /* Q head: 9 action-pairs x 8 hidden */
        #pragma unroll
        for (int a2 = 0; a2 < 9; ++a2) {
            ulonglong2 qa = Qp[a2 * 4 + 0];
            ulonglong2 qb = Qp[a2 * 4 + 1];
            ulonglong2 qc = Qp[a2 * 4 + 2];
            ulonglong2 qd = Qp[a2 * 4 + 3];
            ffma2(acc2[a2], qa.x, f2[0]); ffma2(acc2[a2], qa.y, f2[1]);
            ffma2(acc2[a2], qb.x, f2[2]); ffma2(acc2[a2], qb.y, f2[3]);
            ffma2(acc2[a2], qc.x, f2[4]); ffma2(acc2[a2], qc.y, f2[5]);
            ffma2(acc2[a2], qd.x, f2[6]); ffma2(acc2[a2], qd.y, f2[7]);
        }
    }

    /* combine the 2 gvf parities per row (deterministic) */
    #pragma unroll
    for (int a2 = 0; a2 < 9; ++a2) {
        ull o = __shfl_xor_sync(0xffffffffu, acc2[a2], 1);
        acc2[a2] = addf2(acc2[a2], o);
    }
    if (gpar == 0) {
        ull* P = (ull*)(smf + P_OFF) + (w * ROWS + row) * 9;
        #pragma unroll
        for (int a2 = 0; a2 < 9; ++a2) P[a2] = acc2[a2];
    }
    __syncthreads();   /* weight buffers now free for qW-slice staging */

    /* ---- obs-direct Q tail: double-buffered 256-col slices, 1 barrier/slice ---- */
    {
        ull oacc[9];
        #pragma unroll
        for (int a2 = 0; a2 < 9; ++a2) oacc[a2] = 0ull;
        const float* orow = obs + (size_t)(r0 + w) * OBS_DIMV;

        stage_tail(0, 0, sbase, tid);
        cp_commit();

        #pragma unroll 1
        for (int s = 0; s < NSLICE; ++s) {
            cp_wait<0>();
            __syncthreads();
            if (s + 1 < NSLICE) {
                stage_tail(s + 1, (s + 1) & 1, sbase, tid);
                cp_commit();
            }
            const float* qs = smf + W_OFF + (s & 1) * QO_SLICE_FLOATS;
            #pragma unroll
            for (int jj = 0; jj < 4; ++jj) {
                int jloc = jj * 64 + lane * 2;
                float2 ov = *(const float2*)(orow + s * QO_COLS + jloc);
                ull oA = pack2(ov.x, ov.x);
                ull oB = pack2(ov.y, ov.y);
                #pragma unroll
                for (int a2 = 0; a2 < 9; ++a2) {
                    ulonglong2 qv = *(const ulonglong2*)(qs + a2 * (QO_COLS * 2) + jloc * 2);
                    ffma2(oacc[a2], qv.x, oA);
                    ffma2(oacc[a2], qv.y, oB);
                }
            }
        }

        #pragma unroll
        for (int a2 = 0; a2 < 9; ++a2) {
            #pragma unroll
            for (int off = 16; off >= 1; off >>= 1) {
                ull o = __shfl_xor_sync(0xffffffffu, oacc[a2], off);
                oacc[a2] = addf2(oacc[a2], o);
            }
        }
        if (lane == 0) {
            ull* Po = (ull*)(smf + POBS_OFF) + w * 9;
            #pragma unroll
            for (int a2 = 0; a2 < 9; ++a2) Po[a2] = oacc[a2];
        }
    }
    __syncthreads();

    /* final: 144 threads sum 16 gvf partials + 1 obs partial */
    if (tid < ROWS * 9) {
        int rr = tid / 9;
        int a2 = tid - rr * 9;
        float sx = 0.f, sy = 0.f;
        const ull* P = (const ull*)(smf + P_OFF);
        #pragma unroll
        for (int p = 0; p < NWARP; ++p) {
            float2 v = unpack2(P[(p * ROWS + rr) * 9 + a2]);
            sx += v.x; sy += v.y;
        }
        float2 vo = unpack2(((const ull*)(smf + POBS_OFF))[rr * 9 + a2]);
        sx += vo.x; sy += vo.y;
        out[(size_t)(r0 + rr) * NA + 2 * a2]     = sx;
        out[(size_t)(r0 + rr) * NA + 2 * a2 + 1] = sy;
    }
}

extern "C" void kernel_launch(void* const* d_in, const int* in_sizes, int n_in,
                              void* d_out, int out_size)
{
    const float* obs  = (const float*)d_in[0];
    const float* gvfW = (const float*)d_in[1];
    const float* qW   = (const float*)d_in[2];
    const int*   gidx = (const int*)d_in[3];
    float* out = (float*)d_out;

    repack_kernel<<<(N_TOT + 255) / 256, 256>>>(gvfW, qW, gidx);

    cudaFuncSetAttribute(nibbler_main,
                         cudaFuncAttributeMaxDynamicSharedMemorySize, SMEM_BYTES);
    nibbler_main<<<2048 / ROWS, THREADS, SMEM_BYTES>>>(obs, out);
}

// round 8
// speedup vs baseline: 2.2411x; 1.0880x over previous
#include <cuda_runtime.h>
#include <cuda_fp16.h>
#include <cstdint>

typedef unsigned long long ull;

#define OBS_DIMV 4096
#define NGVF     4096
#define NA       18
#define TF       36864
#define ROWS     16
#define THREADS  512
#define NWARP    16
#define PAIRS    8
#define CHUNK    32
#define NCHUNK   128
#define OSTRIDE_H2 4100

/* per-gvf strides inside a staged chunk (floats) */
#define WSTRIDE  132
#define QSTRIDE  148
#define ISTRIDE  20
#define W_REL    0
#define Q_REL    (CHUNK * WSTRIDE)            /* 4224 */
#define I_REL    (Q_REL + CHUNK * QSTRIDE)    /* 8960 */
#define CH_SZ    (I_REL + CHUNK * ISTRIDE)    /* 9600 floats = 38400 B */
#define CH_BYTES (CH_SZ * 4)

/* obs-direct tail slices */
#define QO_COLS  256
#define QO_SLICE 4608                          /* 9*256*2 floats = 18432 B */
#define QO_BYTES (QO_SLICE * 4)
#define NSLICE   (OBS_DIMV / QO_COLS)          /* 16 */

/* dynamic smem layout (float offsets) */
#define OBS_FLOATS (PAIRS * OSTRIDE_H2)        /* 32800 */
#define CH_OFF   OBS_FLOATS                    /* 32800: two 9600-float bufs */
#define P_OFF    (CH_OFF + 2 * CH_SZ)          /* 52000 */
#define P_FLOATS (NWARP * ROWS * 9 * 2)        /* 4608  */
#define POBS_OFF (P_OFF + P_FLOATS)            /* 56608 */
#define POBS_FLOATS (NWARP * 9 * 2)            /* 288   */
#define MBAR_OFF (POBS_OFF + POBS_FLOATS)      /* 56896 (8 floats = 4 mbarriers) */
#define SMEM_FLOATS (MBAR_OFF + 8)             /* 56904 */
#define SMEM_BYTES  (SMEM_FLOATS * 4)          /* 227616 <= 232448 */

/* ---- repacked, pre-padded, chunk-contiguous weights (rebuilt every launch) ---- */
__device__ __align__(16) float ChunkPk_g[(size_t)NCHUNK * CH_SZ];   /* 4.92 MB */
__device__ __align__(16) float QobsPk_g[NSLICE * QO_SLICE];         /* 295 KB  */

#define N_CH  (NCHUNK * CH_SZ)      /* 1228800 */
#define N_QO  (NSLICE * QO_SLICE)   /* 73728   */
#define N_TOT (N_CH + N_QO)

__global__ void repack_kernel(const float* __restrict__ gvfW,
                              const float* __restrict__ qW,
                              const int*   __restrict__ gidx)
{
    int id = blockIdx.x * 256 + threadIdx.x;
    if (id < N_CH) {
        int c = id / CH_SZ, r = id - c * CH_SZ;
        if (r < Q_REL) {
            int g = r / WSTRIDE, q = r - g * WSTRIDE;
            float v = 0.f;
            if (q < 128) {
                int p = q >> 5, t = q & 31, i = t >> 1, s = t & 1;
                v = gvfW[(size_t)(c * 32 + g) * 128 + (2 * p + s) * 16 + i];
            }
            ChunkPk_g[id] = v;
        } else if (r < I_REL) {
            int r2 = r - Q_REL;
            int g = r2 / QSTRIDE, q = r2 - g * QSTRIDE;
            float v = 0.f;
            if (q < 144) {
                int a2 = q >> 4, t = q & 15, h = t >> 1, s = t & 1;
                v = qW[(size_t)(2 * a2 + s) * TF + OBS_DIMV
                       + (size_t)(c * 32 + g) * 8 + h];
            }
            ChunkPk_g[id] = v;
        } else {
            int r3 = r - I_REL;
            int g = r3 / ISTRIDE, i = r3 - g * ISTRIDE;
            int iv = 0;
            if (i < 16) iv = gidx[(c * 32 + g) * 16 + i] * 4;
            reinterpret_cast<int*>(ChunkPk_g)[id] = iv;
        }
    } else if (id < N_TOT) {
        int t = id - N_CH;
        int s = t / QO_SLICE, r = t - s * QO_SLICE;
        int a2 = r >> 9, u = r & 511, col = u >> 1, sp = u & 1;
        QobsPk_g[t] = qW[(size_t)(2 * a2 + sp) * TF + s * QO_COLS + col];
    }
}

/* ---- mbarrier + bulk-TMA helpers ---- */
__device__ __forceinline__ void mbar_init(uint32_t mbar, uint32_t cnt) {
    asm volatile("mbarrier.init.shared.b64 [%0], %1;" :: "r"(mbar), "r"(cnt) : "memory");
}
__device__ __forceinline__ void mbar_expect_tx(uint32_t mbar, uint32_t bytes) {
    asm volatile("mbarrier.arrive.expect_tx.shared.b64 _, [%0], %1;"
                 :: "r"(mbar), "r"(bytes) : "memory");
}
__device__ __forceinline__ void bulk_g2s(uint32_t dst, const void* src,
                                         uint32_t bytes, uint32_t mbar) {
    asm volatile("cp.async.bulk.shared::cta.global.mbarrier::complete_tx::bytes "
                 "[%0], [%1], %2, [%3];"
                 :: "r"(dst), "l"(src), "r"(bytes), "r"(mbar) : "memory");
}
__device__ __forceinline__ void mbar_wait(uint32_t mbar, uint32_t parity) {
    asm volatile(
        "{\n\t"
        ".reg .pred P;\n"
        "LW_%=:\n\t"
        "mbarrier.try_wait.parity.acquire.cta.shared::cta.b64 P, [%0], %1, 0x989680;\n\t"
        "@P bra.uni LD_%=;\n\t"
        "bra.uni LW_%=;\n"
        "LD_%=:\n\t"
        "}"
        :: "r"(mbar), "r"(parity) : "memory");
}

/* ---- f32x2 helpers ---- */
__device__ __forceinline__ ull pack2(float a, float b) {
    ull r; asm("mov.b64 %0,{%1,%2};" : "=l"(r) : "f"(a), "f"(b)); return r;
}
__device__ __forceinline__ float2 unpack2(ull v) {
    float2 f; asm("mov.b64 {%0,%1},%2;" : "=f"(f.x), "=f"(f.y) : "l"(v)); return f;
}
__device__ __forceinline__ void ffma2(ull& d, ull a, ull b) {
    asm("fma.rn.f32x2 %0,%1,%2,%0;" : "+l"(d) : "l"(a), "l"(b));
}
__device__ __forceinline__ ull addf2(ull a, ull b) {
    ull r; asm("add.rn.f32x2 %0,%1,%2;" : "=l"(r) : "l"(a), "l"(b)); return r;
}
/* dedup'd gather: row-pair lanes load the SAME 32-bit half2 word (broadcast),
   then extract their own half */
__device__ __forceinline__ ull gpk32(const char* obp, int off, int shft) {
    uint32_t v32 = *(const uint32_t*)(obp + off);
    float v = __half2float(__ushort_as_half((unsigned short)(v32 >> shft)));
    return pack2(v, v);
}

extern __shared__ float smf[];

__global__ void __launch_bounds__(THREADS, 1)
nibbler_main(const float* __restrict__ obs, float* __restrict__ out)
{
    const int tid  = threadIdx.x;
    const int w    = tid >> 5;
    const int lane = tid & 31;
    const int gpar = lane & 1;
    const int row  = lane >> 1;
    const int pair = row >> 1;
    const int rh   = row & 1;
    const int shft = rh * 16;
    const int r0   = blockIdx.x * ROWS;

    uint32_t sbase = (uint32_t)__cvta_generic_to_shared(smf);
    const uint32_t MB[2] = { sbase + MBAR_OFF * 4u,      sbase + MBAR_OFF * 4u + 8u };
    const uint32_t MT[2] = { sbase + MBAR_OFF * 4u + 16u, sbase + MBAR_OFF * 4u + 24u };
    const uint32_t CHB[2] = { sbase + CH_OFF * 4u, sbase + (CH_OFF + CH_SZ) * 4u };

    if (tid == 0) {
        mbar_init(MB[0], 1); mbar_init(MB[1], 1);
        mbar_init(MT[0], 1); mbar_init(MT[1], 1);
    }
    __syncthreads();
    if (tid == 0) {
        mbar_expect_tx(MB[0], CH_BYTES);
        bulk_g2s(CHB[0], ChunkPk_g,           CH_BYTES, MB[0]);
        mbar_expect_tx(MB[1], CH_BYTES);
        bulk_g2s(CHB[1], ChunkPk_g + CH_SZ,   CH_BYTES, MB[1]);
    }

    /* stage 16 obs rows into smem as fp16 half2 row-pairs (overlaps TMA) */
    {
        __half2* sObs = reinterpret_cast<__half2*>(smf);
        #pragma unroll 4
        for (int id = tid; id < PAIRS * (OBS_DIMV / 4); id += THREADS) {
            int p = id >> 10, j = id & 1023;
            float4 va = *(const float4*)(obs + (size_t)(r0 + 2 * p    ) * OBS_DIMV + j * 4);
            float4 vb = *(const float4*)(obs + (size_t)(r0 + 2 * p + 1) * OBS_DIMV + j * 4);
            __half2 h0 = __floats2half2_rn(va.x, vb.x);
            __half2 h1 = __floats2half2_rn(va.y, vb.y);
            __half2 h2 = __floats2half2_rn(va.z, vb.z);
            __half2 h3 = __floats2half2_rn(va.w, vb.w);
            uint4 pk;
            pk.x = *reinterpret_cast<uint32_t*>(&h0);
            pk.y = *reinterpret_cast<uint32_t*>(&h1);
            pk.z = *reinterpret_cast<uint32_t*>(&h2);
            pk.w = *reinterpret_cast<uint32_t*>(&h3);
            *(uint4*)(sObs + p * OSTRIDE_H2 + j * 4) = pk;
        }
    }

    const char* obp = (const char*)smf + pair * (OSTRIDE_H2 * 4);
    const int gl = w * 2 + gpar;

    ull acc2[9];
    #pragma unroll
    for (int a = 0; a < 9; ++a) acc2[a] = 0ull;

    /* ---- main loop: mbarrier wait + 1 syncthreads per chunk; 1-thread TMA stage ---- */
    #pragma unroll 1
    for (int c = 0; c < NCHUNK; ++c) {
        mbar_wait(MB[c & 1], (c >> 1) & 1);
        __syncthreads();                       /* all warps finished body(c-1) */
        if (tid == 0 && c >= 1 && c + 1 < NCHUNK) {
            int b2 = (c + 1) & 1;              /* buffer that held chunk c-1 */
            mbar_expect_tx(MB[b2], CH_BYTES);
            bulk_g2s(CHB[b2], ChunkPk_g + (size_t)(c + 1) * CH_SZ, CH_BYTES, MB[b2]);
        }

        const int buf = c & 1;
        const float* chb = smf + CH_OFF + buf * CH_SZ;
        const ulonglong2* Wp = (const ulonglong2*)(chb + gl * WSTRIDE);
        const ulonglong2* Qp = (const ulonglong2*)(chb + Q_REL + gl * QSTRIDE);
        const int4*       I4 = (const int4*)((const int*)(chb + I_REL) + gl * ISTRIDE);

        int4 i0 = I4[0], i1 = I4[1], i2 = I4[2], i3 = I4[3];
        ull x2[16];
        x2[0]  = gpk32(obp, i0.x, shft); x2[1]  = gpk32(obp, i0.y, shft);
        x2[2]  = gpk32(obp, i0.z, shft); x2[3]  = gpk32(obp, i0.w, shft);
        x2[4]  = gpk32(obp, i1.x, shft); x2[5]  = gpk32(obp, i1.y, shft);
        x2[6]  = gpk32(obp, i1.z, shft); x2[7]  = gpk32(obp, i1.w, shft);
        x2[8]  = gpk32(obp, i2.x, shft); x2[9]  = gpk32(obp, i2.y, shft);
        x2[10] = gpk32(obp, i2.z, shft); x2[11] = gpk32(obp, i2.w, shft);
        x2[12] = gpk32(obp, i3.x, shft); x2[13] = gpk32(obp, i3.y, shft);
        x2[14] = gpk32(obp, i3.z, shft); x2[15] = gpk32(obp, i3.w, shft);

        /* hidden: 4 h-pairs x 16 inputs, two parallel chains, ReLU */
        ull f2[8];
        #pragma unroll
        for (int p = 0; p < 4; ++p) {
            ull s0 = 0ull, s1 = 0ull;
            #pragma unroll
            for (int k = 0; k < 4; ++k) {
                ulonglong2 wva = Wp[p * 8 + k];
                ulonglong2 wvb = Wp[p * 8 + 4 + k];
                ffma2(s0, wva.x, x2[2 * k]);
                ffma2(s0, wva.y, x2[2 * k + 1]);
                ffma2(s1, wvb.x, x2[8 + 2 * k]);
                ffma2(s1, wvb.y, x2[8 + 2 * k + 1]);
            }
            ull s = addf2(s0, s1);
            float2 v = unpack2(s);
            float fa = fmaxf(v.x, 0.f), fb = fmaxf(v.y, 0.f);
            f2[2 * p]     = pack2(fa, fa);
            f2[2 * p + 1] = pack2(fb, fb);
        }

        /* Q head: 9 action-pairs x 8 hidden */
        #pragma unroll
        for (int a2 = 0; a2 < 9; ++a2) {
            ulonglong2 qa = Qp[a2 * 4 + 0];
            ulonglong2 qb = Qp[a2 * 4 + 1];
            ulonglong2 qc = Qp[a2 * 4 + 2];
            ulonglong2 qd = Qp[a2 * 4 + 3];
            ffma2(acc2[a2], qa.x, f2[0]); ffma2(acc2[a2], qa.y, f2[1]);
            ffma2(acc2[a2], qb.x, f2[2]); ffma2(acc2[a2], qb.y, f2[3]);
            ffma2(acc2[a2], qc.x, f2[4]); ffma2(acc2[a2], qc.y, f2[5]);
            ffma2(acc2[a2], qd.x, f2[6]); ffma2(acc2[a2], qd.y, f2[7]);
        }
    }

    /* combine the 2 gvf parities per row (deterministic) */
    #pragma unroll
    for (int a2 = 0; a2 < 9; ++a2) {
        ull o = __shfl_xor_sync(0xffffffffu, acc2[a2], 1);
        acc2[a2] = addf2(acc2[a2], o);
    }
    if (gpar == 0) {
        ull* P = (ull*)(smf + P_OFF) + (w * ROWS + row) * 9;
        #pragma unroll
        for (int a2 = 0; a2 < 9; ++a2) P[a2] = acc2[a2];
    }
    __syncthreads();   /* all bodies done -> chunk buffers reusable for tail */

    /* ---- obs-direct Q tail: TMA-staged 256-col slices ---- */
    {
        if (tid == 0) {
            mbar_expect_tx(MT[0], QO_BYTES);
            bulk_g2s(CHB[0], QobsPk_g, QO_BYTES, MT[0]);
            mbar_expect_tx(MT[1], QO_BYTES);
            bulk_g2s(sbase + (CH_OFF + QO_SLICE) * 4u, QobsPk_g + QO_SLICE, QO_BYTES, MT[1]);
        }

        ull oacc[9];
        #pragma unroll
        for (int a2 = 0; a2 < 9; ++a2) oacc[a2] = 0ull;
        const float* orow = obs + (size_t)(r0 + w) * OBS_DIMV;

        #pragma unroll 1
        for (int s = 0; s < NSLICE; ++s) {
            mbar_wait(MT[s & 1], (s >> 1) & 1);
            __syncthreads();
            if (tid == 0 && s >= 1 && s + 1 < NSLICE) {
                int b2 = (s + 1) & 1;
                mbar_expect_tx(MT[b2], QO_BYTES);
                bulk_g2s(sbase + (CH_OFF + b2 * QO_SLICE) * 4u,
                         QobsPk_g + (size_t)(s + 1) * QO_SLICE, QO_BYTES, MT[b2]);
            }
            const float* qs = smf + CH_OFF + (s & 1) * QO_SLICE;
            #pragma unroll
            for (int jj = 0; jj < 4; ++jj) {
                int jloc = jj * 64 + lane * 2;
                float2 ov = *(const float2*)(orow + s * QO_COLS + jloc);
                ull oA = pack2(ov.x, ov.x);
                ull oB = pack2(ov.y, ov.y);
                #pragma unroll
                for (int a2 = 0; a2 < 9; ++a2) {
                    ulonglong2 qv = *(const ulonglong2*)(qs + a2 * (QO_COLS * 2) + jloc * 2);
                    ffma2(oacc[a2], qv.x, oA);
                    ffma2(oacc[a2], qv.y, oB);
                }
            }
        }

        #pragma unroll
        for (int a2 = 0; a2 < 9; ++a2) {
            #pragma unroll
            for (int off = 16; off >= 1; off >>= 1) {
                ull o = __shfl_xor_sync(0xffffffffu, oacc[a2], off);
                oacc[a2] = addf2(oacc[a2], o);
            }
        }
        if (lane == 0) {
            ull* Po = (ull*)(smf + POBS_OFF) + w * 9;
            #pragma unroll
            for (int a2 = 0; a2 < 9; ++a2) Po[a2] = oacc[a2];
        }
    }
    __syncthreads();

    /* final: 144 threads sum 16 gvf partials + 1 obs partial */
    if (tid < ROWS * 9) {
        int rr = tid / 9;
        int a2 = tid - rr * 9;
        float sx = 0.f, sy = 0.f;
        const ull* P = (const ull*)(smf + P_OFF);
        #pragma unroll
        for (int p = 0; p < NWARP; ++p) {
            float2 v = unpack2(P[(p * ROWS + rr) * 9 + a2]);
            sx += v.x; sy += v.y;
        }
        float2 vo = unpack2(((const ull*)(smf + POBS_OFF))[rr * 9 + a2]);
        sx += vo.x; sy += vo.y;
        out[(size_t)(r0 + rr) * NA + 2 * a2]     = sx;
        out[(size_t)(r0 + rr) * NA + 2 * a2 + 1] = sy;
    }
}

extern "C" void kernel_launch(void* const* d_in, const int* in_sizes, int n_in,
                              void* d_out, int out_size)
{
    const float* obs  = (const float*)d_in[0];
    const float* gvfW = (const float*)d_in[1];
    const float* qW   = (const float*)d_in[2];
    const int*   gidx = (const int*)d_in[3];
    float* out = (float*)d_out;

    repack_kernel<<<(N_TOT + 255) / 256, 256>>>(gvfW, qW, gidx);

    cudaFuncSetAttribute(nibbler_main,
                         cudaFuncAttributeMaxDynamicSharedMemorySize, SMEM_BYTES);
    nibbler_main<<<2048 / ROWS, THREADS, SMEM_BYTES>>>(obs, out);
}

// round 11
// speedup vs baseline: 2.4361x; 1.0870x over previous
#include <cuda_runtime.h>
#include <cuda_fp16.h>
#include <cstdint>

typedef unsigned long long ull;

#define OBS_DIMV 4096
#define NGVF     4096
#define NA       18
#define TF       36864
#define ROWS     16
#define THREADS  512
#define NWARP    16
#define PAIRS    8
#define OSTRIDE_H2 4100

/* 8-gvf chunks, 4 warp-sets (4 warps each), 2 buffers per set */
#define NSET     4
#define CH8      8
#define NCH      128          /* chunks per set */
#define WSTRIDE  132
#define QSTRIDE  148
#define ISTRIDE  20
#define Q_REL    (CH8 * WSTRIDE)              /* 1056 */
#define I_REL    (Q_REL + CH8 * QSTRIDE)      /* 2240 */
#define CH_SZ    (I_REL + CH8 * ISTRIDE)      /* 2400 floats = 9600 B */
#define CH_BYTES (CH_SZ * 4)

/* obs-direct tail slices */
#define QO_COLS  256
#define QO_SLICE 4608
#define QO_BYTES (QO_SLICE * 4)
#define NSLICE   (OBS_DIMV / QO_COLS)

/* dynamic smem layout (float offsets) */
#define OBS_FLOATS (PAIRS * OSTRIDE_H2)        /* 32800 */
#define CH_OFF   OBS_FLOATS                    /* 8 bufs x 2400 = 19200 */
#define P_OFF    (CH_OFF + 8 * CH_SZ)          /* 52000 */
#define P_FLOATS (NWARP * ROWS * 9 * 2)        /* 4608  */
#define POBS_OFF (P_OFF + P_FLOATS)            /* 56608 */
#define POBS_FLOATS (NWARP * 9 * 2)            /* 288   */
#define MBAR_OFF (POBS_OFF + POBS_FLOATS)      /* 56896; 10 mbarriers = 20 floats */
#define SMEM_FLOATS (MBAR_OFF + 20)            /* 56916 */
#define SMEM_BYTES  (SMEM_FLOATS * 4)          /* 227664 <= 232448 */

/* ---- repacked weights (rebuilt every launch) ---- */
__device__ __align__(16) float ChunkPk_g[(size_t)NSET * NCH * CH_SZ];  /* 4.92 MB */
__device__ __align__(16) float QobsPk_g[NSLICE * QO_SLICE];

#define N_CH  (NSET * NCH * CH_SZ)
#define N_QO  (NSLICE * QO_SLICE)
#define N_TOT (N_CH + N_QO)

__global__ void repack_kernel(const float* __restrict__ gvfW,
                              const float* __restrict__ qW,
                              const int*   __restrict__ gidx)
{
    int id = blockIdx.x * 256 + threadIdx.x;
    if (id < N_CH) {
        int bc = id / CH_SZ, r = id - bc * CH_SZ;
        int s = bc >> 7, c = bc & 127;
        int gbase = s * 1024 + c * 8;
        if (r < Q_REL) {
            int g = r / WSTRIDE, q = r - g * WSTRIDE;
            float v = 0.f;
            if (q < 128) {
                int p = q >> 5, t = q & 31, i = t >> 1, sp = t & 1;
                v = gvfW[(size_t)(gbase + g) * 128 + (2 * p + sp) * 16 + i];
            }
            ChunkPk_g[id] = v;
        } else if (r < I_REL) {
            int r2 = r - Q_REL;
            int g = r2 / QSTRIDE, q = r2 - g * QSTRIDE;
            float v = 0.f;
            if (q < 144) {
                int a2 = q >> 4, t = q & 15, h = t >> 1, sp = t & 1;
                v = qW[(size_t)(2 * a2 + sp) * TF + OBS_DIMV
                       + (size_t)(gbase + g) * 8 + h];
            }
            ChunkPk_g[id] = v;
        } else {
            int r3 = r - I_REL;
            int g = r3 / ISTRIDE, i = r3 - g * ISTRIDE;
            int iv = 0;
            if (i < 16) iv = gidx[(gbase + g) * 16 + i] * 4;
            reinterpret_cast<int*>(ChunkPk_g)[id] = iv;
        }
    } else if (id < N_TOT) {
        int t = id - N_CH;
        int s = t / QO_SLICE, r = t - s * QO_SLICE;
        int a2 = r >> 9, u = r & 511, col = u >> 1, sp = u & 1;
        QobsPk_g[t] = qW[(size_t)(2 * a2 + sp) * TF + s * QO_COLS + col];
    }
}

/* ---- mbarrier + bulk-TMA helpers ---- */
__device__ __forceinline__ void mbar_init(uint32_t mbar, uint32_t cnt) {
    asm volatile("mbarrier.init.shared.b64 [%0], %1;" :: "r"(mbar), "r"(cnt) : "memory");
}
__device__ __forceinline__ void mbar_expect_tx(uint32_t mbar, uint32_t bytes) {
    asm volatile("mbarrier.arrive.expect_tx.shared.b64 _, [%0], %1;"
                 :: "r"(mbar), "r"(bytes) : "memory");
}
__device__ __forceinline__ void bulk_g2s(uint32_t dst, const void* src,
                                         uint32_t bytes, uint32_t mbar) {
    asm volatile("cp.async.bulk.shared::cta.global.mbarrier::complete_tx::bytes "
                 "[%0], [%1], %2, [%3];"
                 :: "r"(dst), "l"(src), "r"(bytes), "r"(mbar) : "memory");
}
__device__ __forceinline__ void mbar_wait(uint32_t mbar, uint32_t parity) {
    asm volatile(
        "{\n\t"
        ".reg .pred P;\n"
        "LW_%=:\n\t"
        "mbarrier.try_wait.parity.acquire.cta.shared::cta.b64 P, [%0], %1, 0x989680;\n\t"
        "@P bra.uni LD_%=;\n\t"
        "bra.uni LW_%=;\n"
        "LD_%=:\n\t"
        "}"
        :: "r"(mbar), "r"(parity) : "memory");
}
__device__ __forceinline__ void set_bar(int id) {
    asm volatile("bar.sync %0, 128;" :: "r"(id) : "memory");
}
__device__ __forceinline__ void fence_async() {
    asm volatile("fence.proxy.async.shared::cta;" ::: "memory");
}

/* ---- f32x2 helpers ---- */
__device__ __forceinline__ ull pack2(float a, float b) {
    ull r; asm("mov.b64 %0,{%1,%2};" : "=l"(r) : "f"(a), "f"(b)); return r;
}
__device__ __forceinline__ float2 unpack2(ull v) {
    float2 f; asm("mov.b64 {%0,%1},%2;" : "=f"(f.x), "=f"(f.y) : "l"(v)); return f;
}
__device__ __forceinline__ void ffma2(ull& d, ull a, ull b) {
    asm("fma.rn.f32x2 %0,%1,%2,%0;" : "+l"(d) : "l"(a), "l"(b));
}
__device__ __forceinline__ ull addf2(ull a, ull b) {
    ull r; asm("add.rn.f32x2 %0,%1,%2;" : "=l"(r) : "l"(a), "l"(b)); return r;
}
__device__ __forceinline__ ull gpk32(const char* obp, int off, int shft) {
    uint32_t v32 = *(const uint32_t*)(obp + off);
    float v = __half2float(__ushort_as_half((unsigned short)(v32 >> shft)));
    return pack2(v, v);
}

extern __shared__ float smf[];

__global__ void __launch_bounds__(THREADS, 1)
nibbler_main(const float* __restrict__ obs, float* __restrict__ out)
{
    const int tid  = threadIdx.x;
    const int w    = tid >> 5;
    const int lane = tid & 31;
    const int gpar = lane & 1;
    const int row  = lane >> 1;
    const int pair = row >> 1;
    const int rh   = row & 1;
    const int shft = rh * 16;
    const int set  = w >> 2;            /* warp-set 0..3 (4 warps each) */
    const int r0   = blockIdx.x * ROWS;

    uint32_t sbase = (uint32_t)__cvta_generic_to_shared(smf);
    const uint32_t MBASE = sbase + MBAR_OFF * 4u;
    /* full[set][b] @ MBASE + (set*2+b)*8 ; tail MT at +64, +72 */
    const uint32_t MT[2] = { MBASE + 64u, MBASE + 72u };

    if (tid == 0) {
        #pragma unroll
        for (int i = 0; i < 8; ++i) mbar_init(MBASE + (uint32_t)i * 8u, 1);
        mbar_init(MT[0], 1);
        mbar_init(MT[1], 1);
    }
    __syncthreads();

    const bool producer = (tid == set * 128);
    const uint32_t MBf0 = MBASE + (uint32_t)(set * 2) * 8u;
    const uint32_t CHB0 = sbase + (uint32_t)(CH_OFF + set * 2 * CH_SZ) * 4u;
    const float*   SRC0 = ChunkPk_g + (size_t)set * NCH * CH_SZ;

    if (producer) {
        mbar_expect_tx(MBf0, CH_BYTES);
        bulk_g2s(CHB0, SRC0, CH_BYTES, MBf0);
        mbar_expect_tx(MBf0 + 8u, CH_BYTES);
        bulk_g2s(CHB0 + CH_BYTES, SRC0 + CH_SZ, CH_BYTES, MBf0 + 8u);
    }

    /* stage 16 obs rows into smem as fp16 half2 row-pairs (overlaps TMA) */
    {
        __half2* sObs = reinterpret_cast<__half2*>(smf);
        #pragma unroll 4
        for (int id = tid; id < PAIRS * (OBS_DIMV / 4); id += THREADS) {
            int p = id >> 10, j = id & 1023;
            float4 va = *(const float4*)(obs + (size_t)(r0 + 2 * p    ) * OBS_DIMV + j * 4);
            float4 vb = *(const float4*)(obs + (size_t)(r0 + 2 * p + 1) * OBS_DIMV + j * 4);
            __half2 h0 = __floats2half2_rn(va.x, vb.x);
            __half2 h1 = __floats2half2_rn(va.y, vb.y);
            __half2 h2 = __floats2half2_rn(va.z, vb.z);
            __half2 h3 = __floats2half2_rn(va.w, vb.w);
            uint4 pk;
            pk.x = *reinterpret_cast<uint32_t*>(&h0);
            pk.y = *reinterpret_cast<uint32_t*>(&h1);
            pk.z = *reinterpret_cast<uint32_t*>(&h2);
            pk.w = *reinterpret_cast<uint32_t*>(&h3);
            *(uint4*)(sObs + p * OSTRIDE_H2 + j * 4) = pk;
        }
    }
    __syncthreads();   /* obs ready for gathers */

    const char* obp = (const char*)smf + pair * (OSTRIDE_H2 * 4);
    const int gl = 2 * (w & 3) + gpar;   /* gvf index within this set's 8-gvf chunk */

    ull acc2[9];
    #pragma unroll
    for (int a = 0; a < 9; ++a) acc2[a] = 0ull;

    /* ---- main loop: per-set TMA pipeline; ONE named set-barrier per chunk.
       Safety: full waits are mbarrier (staged in order, parity (c>>1)&1);
       buffer reuse is ordered by bar.sync(1+set) which ALL 128 set-threads
       reach unconditionally -> no deadlock mode. ---- */
    #pragma unroll 1
    for (int c = 0; c < NCH; ++c) {
        const int b = c & 1;
        mbar_wait(MBf0 + (uint32_t)b * 8u, (c >> 1) & 1);

        const float* chb = smf + CH_OFF + (set * 2 + b) * CH_SZ;
        const ulonglong2* Wp = (const ulonglong2*)(chb + gl * WSTRIDE);
        const ulonglong2* Qp = (const ulonglong2*)(chb + Q_REL + gl * QSTRIDE);
        const int4*       I4 = (const int4*)((const int*)(chb + I_REL) + gl * ISTRIDE);

        int4 i0 = I4[0], i1 = I4[1], i2 = I4[2], i3 = I4[3];
        ull x2[16];
        x2[0]  = gpk32(obp, i0.x, shft); x2[1]  = gpk32(obp, i0.y, shft);
        x2[2]  = gpk32(obp, i0.z, shft); x2[3]  = gpk32(obp, i0.w, shft);
        x2[4]  = gpk32(obp, i1.x, shft); x2[5]  = gpk32(obp, i1.y, shft);
        x2[6]  = gpk32(obp, i1.z, shft); x2[7]  = gpk32(obp, i1.w, shft);
        x2[8]  = gpk32(obp, i2.x, shft); x2[9]  = gpk32(obp, i2.y, shft);
        x2[10] = gpk32(obp, i2.z, shft); x2[11] = gpk32(obp, i2.w, shft);
        x2[12] = gpk32(obp, i3.x, shft); x2[13] = gpk32(obp, i3.y, shft);
        x2[14] = gpk32(obp, i3.z, shft); x2[15] = gpk32(obp, i3.w, shft);

        /* hidden: 4 h-pairs x 16 inputs, two parallel chains, ReLU */
        ull f2[8];
        #pragma unroll
        for (int p = 0; p < 4; ++p) {
            ull s0 = 0ull, s1 = 0ull;
            #pragma unroll
            for (int k = 0; k < 4; ++k) {
                ulonglong2 wva = Wp[p * 8 + k];
                ulonglong2 wvb = Wp[p * 8 + 4 + k];
                ffma2(s0, wva.x, x2[2 * k]);
                ffma2(s0, wva.y, x2[2 * k + 1]);
                ffma2(s1, wvb.x, x2[8 + 2 * k]);
                ffma2(s1, wvb.y, x2[8 + 2 * k + 1]);
            }
            ull s = addf2(s0, s1);
            float2 v = unpack2(s);
            float fa = fmaxf(v.x, 0.f), fb = fmaxf(v.y, 0.f);
            f2[2 * p]     = pack2(fa, fa);
            f2[2 * p + 1] = pack2(fb, fb);
        }

        /* Q head: 9 action-pairs x 8 hidden */
        #pragma unroll
        for (int a2 = 0; a2 < 9; ++a2) {
            ulonglong2 qa = Qp[a2 * 4 + 0];
            ulonglong2 qb = Qp[a2 * 4 + 1];
            ulonglong2 qc = Qp[a2 * 4 + 2];
            ulonglong2 qd = Qp[a2 * 4 + 3];
            ffma2(acc2[a2], qa.x, f2[0]); ffma2(acc2[a2], qa.y, f2[1]);
            ffma2(acc2[a2], qb.x, f2[2]); ffma2(acc2[a2], qb.y, f2[3]);
            ffma2(acc2[a2], qc.x, f2[4]); ffma2(acc2[a2], qc.y, f2[5]);
            ffma2(acc2[a2], qd.x, f2[6]); ffma2(acc2[a2], qd.y, f2[7]);
        }

        /* all 4 warps of the set done reading buffer b */
        set_bar(1 + set);
        if (producer && c + 2 < NCH) {
            fence_async();
            mbar_expect_tx(MBf0 + (uint32_t)b * 8u, CH_BYTES);
            bulk_g2s(CHB0 + (uint32_t)b * CH_BYTES,
                     SRC0 + (size_t)(c + 2) * CH_SZ, CH_BYTES,
                     MBf0 + (uint32_t)b * 8u);
        }
    }

    /* combine the 2 gvf parities per row (deterministic) */
    #pragma unroll
    for (int a2 = 0; a2 < 9; ++a2) {
        ull o = __shfl_xor_sync(0xffffffffu, acc2[a2], 1);
        acc2[a2] = addf2(acc2[a2], o);
    }
    if (gpar == 0) {
        ull* P = (ull*)(smf + P_OFF) + (w * ROWS + row) * 9;
        #pragma unroll
        for (int a2 = 0; a2 < 9; ++a2) P[a2] = acc2[a2];
    }
    __syncthreads();   /* all warps done -> chunk buffers reusable for tail */

    /* ---- obs-direct Q tail: TMA-staged 256-col slices (R8-proven) ---- */
    {
        uint32_t TB0 = sbase + (uint32_t)CH_OFF * 4u;
        if (tid == 0) {
            mbar_expect_tx(MT[0], QO_BYTES);
            bulk_g2s(TB0, QobsPk_g, QO_BYTES, MT[0]);
            mbar_expect_tx(MT[1], QO_BYTES);
            bulk_g2s(TB0 + QO_BYTES, QobsPk_g + QO_SLICE, QO_BYTES, MT[1]);
        }

        ull oacc[9];
        #pragma unroll
        for (int a2 = 0; a2 < 9; ++a2) oacc[a2] = 0ull;
        const float* orow = obs + (size_t)(r0 + w) * OBS_DIMV;

        #pragma unroll 1
        for (int s = 0; s < NSLICE; ++s) {
            mbar_wait(MT[s & 1], (s >> 1) & 1);
            __syncthreads();
            if (tid == 0 && s >= 1 && s + 1 < NSLICE) {
                int b2 = (s + 1) & 1;
                mbar_expect_tx(MT[b2], QO_BYTES);
                bulk_g2s(TB0 + (uint32_t)b2 * QO_BYTES,
                         QobsPk_g + (size_t)(s + 1) * QO_SLICE, QO_BYTES, MT[b2]);
            }
            const float* qs = smf + CH_OFF + (s & 1) * QO_SLICE;
            #pragma unroll
            for (int jj = 0; jj < 4; ++jj) {
                int jloc = jj * 64 + lane * 2;
                float2 ov = *(const float2*)(orow + s * QO_COLS + jloc);
                ull oA = pack2(ov.x, ov.x);
                ull oB = pack2(ov.y, ov.y);
                #pragma unroll
                for (int a2 = 0; a2 < 9; ++a2) {
                    ulonglong2 qv = *(const ulonglong2*)(qs + a2 * (QO_COLS * 2) + jloc * 2);
                    ffma2(oacc[a2], qv.x, oA);
                    ffma2(oacc[a2], qv.y, oB);
                }
            }
        }

        #pragma unroll
        for (int a2 = 0; a2 < 9; ++a2) {
            #pragma unroll
            for (int off = 16; off >= 1; off >>= 1) {
                ull o = __shfl_xor_sync(0xffffffffu, oacc[a2], off);
                oacc[a2] = addf2(oacc[a2], o);
            }
        }
        if (lane == 0) {
            ull* Po = (ull*)(smf + POBS_OFF) + w * 9;
            #pragma unroll
            for (int a2 = 0; a2 < 9; ++a2) Po[a2] = oacc[a2];
        }
    }
    __syncthreads();

    /* final: 144 threads sum 16 gvf partials + 1 obs partial */
    if (tid < ROWS * 9) {
        int rr = tid / 9;
        int a2 = tid - rr * 9;
        float sx = 0.f, sy = 0.f;
        const ull* P = (const ull*)(smf + P_OFF);
        #pragma unroll
        for (int p = 0; p < NWARP; ++p) {
            float2 v = unpack2(P[(p * ROWS + rr) * 9 + a2]);
            sx += v.x; sy += v.y;
        }
        float2 vo = unpack2(((const ull*)(smf + POBS_OFF))[rr * 9 + a2]);
        sx += vo.x; sy += vo.y;
        out[(size_t)(r0 + rr) * NA + 2 * a2]     = sx;
        out[(size_t)(r0 + rr) * NA + 2 * a2 + 1] = sy;
    }
}

extern "C" void kernel_launch(void* const* d_in, const int* in_sizes, int n_in,
                              void* d_out, int out_size)
{
    const float* obs  = (const float*)d_in[0];
    const float* gvfW = (const float*)d_in[1];
    const float* qW   = (const float*)d_in[2];
    const int*   gidx = (const int*)d_in[3];
    float* out = (float*)d_out;

    repack_kernel<<<(N_TOT + 255) / 256, 256>>>(gvfW, qW, gidx);

    cudaFuncSetAttribute(nibbler_main,
                         cudaFuncAttributeMaxDynamicSharedMemorySize, SMEM_BYTES);
    nibbler_main<<<2048 / ROWS, THREADS, SMEM_BYTES>>>(obs, out);
}

// round 12
// speedup vs baseline: 5.9064x; 2.4245x over previous
#include <cuda_runtime.h>
#include <cuda_fp16.h>
#include <cstdint>

typedef unsigned long long ull;

#define OBS_DIMV 4096
#define NGVF     4096
#define NA       18
#define TF       36864
#define ROWS     16
#define THREADS  512
#define NWARP    16
#define PAIRS    8
#define OSTRIDE_H2 4100          /* half2 words per pair-row (4096 + 4 pad) */

/* 8-gvf chunks, 4 warp-sets (4 warps each), 3 buffers per set */
#define NSET     4
#define NBUF     3
#define NCH      128             /* chunks per set */
/* chunk layout (u32 words): idx 128 | W 512 | Q 768  = 1408 words = 5632 B */
#define CHW32    1408
#define CH_BYTES (CHW32 * 4)
#define IDX_REL  0               /* bytes */
#define W_RELB   512
#define Q_RELB   2560

/* obs-direct tail slices (fp32, unchanged from R8) */
#define QO_COLS  256
#define QO_SLICE 4608            /* floats */
#define QO_BYTES (QO_SLICE * 4)
#define NSLICE   (OBS_DIMV / QO_COLS)

/* smem byte offsets */
#define OBS_B    0
#define OBS_BYTES (PAIRS * OSTRIDE_H2 * 4)        /* 131200 */
#define CH_B     OBS_BYTES                        /* 12 bufs x 5632 = 67584 */
#define P_B      (CH_B + NSET * NBUF * CH_BYTES)  /* 198784 */
#define P_BYTES  (NWARP * ROWS * 24 * 4)          /* 24576  */
#define POBS_B   (P_B + P_BYTES)                  /* 223360 */
#define POBS_BYTES (NWARP * NA * 4)               /* 1152   */
#define MBAR_B   (POBS_B + POBS_BYTES)            /* 224512; 14 mbarriers */
#define SMEM_BYTES (MBAR_B + 128)                 /* 224640 <= 232448 */

/* ---- repacked weights (rebuilt every launch) ---- */
__device__ __align__(16) uint32_t ChunkPk_g[(size_t)NSET * NCH * CHW32]; /* 2.88MB */
__device__ __align__(16) float    QobsPk_g[NSLICE * QO_SLICE];

#define N_CHW (NSET * NCH * CHW32)   /* 720896 */
#define N_QO  (NSLICE * QO_SLICE)    /* 73728  */
#define N_TOT (N_CHW + N_QO)

__global__ void repack_kernel(const float* __restrict__ gvfW,
                              const float* __restrict__ qW,
                              const int*   __restrict__ gidx)
{
    int id = blockIdx.x * 256 + threadIdx.x;
    if (id < N_CHW) {
        int sc = id / CHW32;
        int r  = id - sc * CHW32;
        int gbase = (sc >> 7) * 1024 + (sc & 127) * 8;
        uint32_t val;
        if (r < 128) {
            /* idx int4 table: [g][t] = (i2t, i2t+1, i2t+8, i2t+9)*4 */
            int g = r >> 4, t = (r >> 2) & 3, comp = r & 3;
            int i = (comp < 2) ? (2 * t + comp) : (2 * t + 8 + (comp - 2));
            val = (uint32_t)(gidx[(gbase + g) * 16 + i] * 4);
        } else if (r < 640) {
            /* W b-frag table: [g][lane][half]: f16x2 (lo = B[k0][h], hi = B[k0+1][h]) */
            int w2 = r - 128;
            int g = w2 >> 6, rem = w2 & 63;
            int lane = rem >> 1, half = rem & 1;
            int h = lane >> 2, t = lane & 3;
            int k0 = half ? (2 * t + 8) : (2 * t);
            float f0 = gvfW[((size_t)(gbase + g) * 8 + h) * 16 + k0];
            float f1 = gvfW[((size_t)(gbase + g) * 8 + h) * 16 + k0 + 1];
            __half2 hh = __floats2half2_rn(f0, f1);
            val = *reinterpret_cast<uint32_t*>(&hh);
        } else {
            /* Q b-frag table: [p][tile][lane][half] */
            int qd = r - 640;
            int p = qd / 192, rem = qd - p * 192;
            int tile = rem >> 6, rem2 = rem & 63;
            int lane = rem2 >> 1, half = rem2 & 1;
            int n = (lane >> 2) + tile * 8, t = lane & 3;
            int k0 = half ? (2 * t + 8) : (2 * t);
            float q0 = 0.f, q1 = 0.f;
            if (n < 18) {
                int gv = gbase + p * 2 + (k0 >> 3);
                int h0 = k0 & 7;
                q0 = qW[(size_t)n * TF + OBS_DIMV + (size_t)gv * 8 + h0];
                q1 = qW[(size_t)n * TF + OBS_DIMV + (size_t)gv * 8 + h0 + 1];
            }
            __half2 hh = __floats2half2_rn(q0, q1);
            val = *reinterpret_cast<uint32_t*>(&hh);
        }
        ChunkPk_g[id] = val;
    } else if (id < N_TOT) {
        int t = id - N_CHW;
        int s = t / QO_SLICE, r = t - s * QO_SLICE;
        int a2 = r >> 9, u = r & 511, col = u >> 1, sp = u & 1;
        QobsPk_g[t] = qW[(size_t)(2 * a2 + sp) * TF + s * QO_COLS + col];
    }
}

/* ---- mbarrier + bulk-TMA helpers ---- */
__device__ __forceinline__ void mbar_init(uint32_t mbar, uint32_t cnt) {
    asm volatile("mbarrier.init.shared.b64 [%0], %1;" :: "r"(mbar), "r"(cnt) : "memory");
}
__device__ __forceinline__ void mbar_expect_tx(uint32_t mbar, uint32_t bytes) {
    asm volatile("mbarrier.arrive.expect_tx.shared.b64 _, [%0], %1;"
                 :: "r"(mbar), "r"(bytes) : "memory");
}
__device__ __forceinline__ void bulk_g2s(uint32_t dst, const void* src,
                                         uint32_t bytes, uint32_t mbar) {
    asm volatile("cp.async.bulk.shared::cta.global.mbarrier::complete_tx::bytes "
                 "[%0], [%1], %2, [%3];"
                 :: "r"(dst), "l"(src), "r"(bytes), "r"(mbar) : "memory");
}
__device__ __forceinline__ void mbar_wait(uint32_t mbar, uint32_t parity) {
    asm volatile(
        "{\n\t"
        ".reg .pred P;\n"
        "LW_%=:\n\t"
        "mbarrier.try_wait.parity.acquire.cta.shared::cta.b64 P, [%0], %1, 0x989680;\n\t"
        "@P bra.uni LD_%=;\n\t"
        "bra.uni LW_%=;\n"
        "LD_%=:\n\t"
        "}"
        :: "r"(mbar), "r"(parity) : "memory");
}
__device__ __forceinline__ void set_bar(int id) {
    asm volatile("bar.sync %0, 128;" :: "r"(id) : "memory");
}
__device__ __forceinline__ void fence_async() {
    asm volatile("fence.proxy.async.shared::cta;" ::: "memory");
}

/* ---- mma + cvt helpers ---- */
__device__ __forceinline__ void mma16816(float& d0, float& d1, float& d2, float& d3,
    uint32_t a0, uint32_t a1, uint32_t a2, uint32_t a3,
    uint32_t b0, uint32_t b1,
    float c0, float c1, float c2, float c3)
{
    asm volatile("mma.sync.aligned.m16n8k16.row.col.f32.f16.f16.f32 "
        "{%0,%1,%2,%3},{%4,%5,%6,%7},{%8,%9},{%10,%11,%12,%13};"
        : "=f"(d0), "=f"(d1), "=f"(d2), "=f"(d3)
        : "r"(a0), "r"(a1), "r"(a2), "r"(a3), "r"(b0), "r"(b1),
          "f"(c0), "f"(c1), "f"(c2), "f"(c3));
}
__device__ __forceinline__ uint32_t cvt_f16x2(float hi, float lo) {
    uint32_t r; asm("cvt.rn.f16x2.f32 %0, %1, %2;" : "=r"(r) : "f"(hi), "f"(lo)); return r;
}

/* ---- f32x2 helpers (tail only) ---- */
__device__ __forceinline__ ull pack2(float a, float b) {
    ull r; asm("mov.b64 %0,{%1,%2};" : "=l"(r) : "f"(a), "f"(b)); return r;
}
__device__ __forceinline__ float2 unpack2(ull v) {
    float2 f; asm("mov.b64 {%0,%1},%2;" : "=f"(f.x), "=f"(f.y) : "l"(v)); return f;
}
__device__ __forceinline__ void ffma2(ull& d, ull a, ull b) {
    asm("fma.rn.f32x2 %0,%1,%2,%0;" : "+l"(d) : "l"(a), "l"(b));
}
__device__ __forceinline__ ull addf2(ull a, ull b) {
    ull r; asm("add.rn.f32x2 %0,%1,%2;" : "=l"(r) : "l"(a), "l"(b)); return r;
}

extern __shared__ float smf[];

__global__ void __launch_bounds__(THREADS, 1)
nibbler_main(const float* __restrict__ obs, float* __restrict__ out)
{
    const int tid  = threadIdx.x;
    const int w    = tid >> 5;
    const int lane = tid & 31;
    const int set  = w >> 2;           /* warp-set 0..3 */
    const int p    = w & 3;            /* gvf-pair slot within set's 8-gvf chunk */
    const int g    = lane >> 2;        /* mma row group (rows g and g+8) */
    const int t    = lane & 3;         /* thread-in-group */
    const int r0   = blockIdx.x * ROWS;

    char* smb = (char*)smf;
    uint32_t sbase = (uint32_t)__cvta_generic_to_shared(smf);
    const uint32_t MBASE = sbase + MBAR_B;
    const uint32_t MT[2] = { MBASE + 96u, MBASE + 104u };

    if (tid == 0) {
        #pragma unroll
        for (int i = 0; i < NSET * NBUF; ++i) mbar_init(MBASE + (uint32_t)i * 8u, 1);
        mbar_init(MT[0], 1);
        mbar_init(MT[1], 1);
    }
    __syncthreads();

    const bool producer = (tid == set * 128);
    const uint32_t MBf = MBASE + (uint32_t)(set * NBUF) * 8u;
    const uint32_t CHB = sbase + (uint32_t)(CH_B + set * NBUF * CH_BYTES);
    const uint32_t* SRC = ChunkPk_g + (size_t)set * NCH * CHW32;

    if (producer) {
        #pragma unroll
        for (int b = 0; b < NBUF; ++b) {
            mbar_expect_tx(MBf + (uint32_t)b * 8u, CH_BYTES);
            bulk_g2s(CHB + (uint32_t)b * CH_BYTES, SRC + (size_t)b * CHW32,
                     CH_BYTES, MBf + (uint32_t)b * 8u);
        }
    }

    /* stage obs as half2 row-pairs (row p low, row p+8 high) */
    {
        __half2* sObs = reinterpret_cast<__half2*>(smf);
        #pragma unroll 4
        for (int id = tid; id < PAIRS * (OBS_DIMV / 4); id += THREADS) {
            int pp = id >> 10, j = id & 1023;
            float4 va = *(const float4*)(obs + (size_t)(r0 + pp    ) * OBS_DIMV + j * 4);
            float4 vb = *(const float4*)(obs + (size_t)(r0 + pp + 8) * OBS_DIMV + j * 4);
            __half2 h0 = __floats2half2_rn(va.x, vb.x);
            __half2 h1 = __floats2half2_rn(va.y, vb.y);
            __half2 h2 = __floats2half2_rn(va.z, vb.z);
            __half2 h3 = __floats2half2_rn(va.w, vb.w);
            uint4 pk;
            pk.x = *reinterpret_cast<uint32_t*>(&h0);
            pk.y = *reinterpret_cast<uint32_t*>(&h1);
            pk.z = *reinterpret_cast<uint32_t*>(&h2);
            pk.w = *reinterpret_cast<uint32_t*>(&h3);
            *(uint4*)(sObs + pp * OSTRIDE_H2 + j * 4) = pk;
        }
    }
    __syncthreads();

    const char* obp = smb + g * (OSTRIDE_H2 * 4);

    /* Q-head accumulators: 3 n-tiles x 4 fp32 */
    float D00 = 0.f, D01 = 0.f, D02 = 0.f, D03 = 0.f;
    float D10 = 0.f, D11 = 0.f, D12 = 0.f, D13 = 0.f;
    float D20 = 0.f, D21 = 0.f, D22 = 0.f, D23 = 0.f;

    #pragma unroll 1
    for (int c = 0; c < NCH; ++c) {
        const int b = c % NBUF;
        mbar_wait(MBf + (uint32_t)b * 8u, (c / NBUF) & 1);

        const char* chb = smb + CH_B + (set * NBUF + b) * CH_BYTES;

        /* idx frag tables */
        int4 iv0 = ((const int4*)chb)[(2 * p) * 4 + t];
        int4 iv1 = ((const int4*)chb)[(2 * p + 1) * 4 + t];

        /* gather + A-fragment build (gvf0) */
        uint32_t wa = *(const uint32_t*)(obp + iv0.x);
        uint32_t wb = *(const uint32_t*)(obp + iv0.y);
        uint32_t wc = *(const uint32_t*)(obp + iv0.z);
        uint32_t wd = *(const uint32_t*)(obp + iv0.w);
        uint32_t A00 = __byte_perm(wa, wb, 0x5410);
        uint32_t A01 = __byte_perm(wa, wb, 0x7632);
        uint32_t A02 = __byte_perm(wc, wd, 0x5410);
        uint32_t A03 = __byte_perm(wc, wd, 0x7632);
        /* gvf1 */
        uint32_t xa = *(const uint32_t*)(obp + iv1.x);
        uint32_t xb = *(const uint32_t*)(obp + iv1.y);
        uint32_t xc = *(const uint32_t*)(obp + iv1.z);
        uint32_t xd = *(const uint32_t*)(obp + iv1.w);
        uint32_t A10 = __byte_perm(xa, xb, 0x5410);
        uint32_t A11 = __byte_perm(xa, xb, 0x7632);
        uint32_t A12 = __byte_perm(xc, xd, 0x5410);
        uint32_t A13 = __byte_perm(xc, xd, 0x7632);

        /* hidden mma (per gvf): f[16 rows x 8 h] = X[16x16] * W[16x8] */
        uint2 Wf0 = *(const uint2*)(chb + W_RELB + (2 * p) * 256 + lane * 8);
        uint2 Wf1 = *(const uint2*)(chb + W_RELB + (2 * p + 1) * 256 + lane * 8);
        float h00, h01, h02, h03, h10, h11, h12, h13;
        mma16816(h00, h01, h02, h03, A00, A01, A02, A03, Wf0.x, Wf0.y,
                 0.f, 0.f, 0.f, 0.f);
        mma16816(h10, h11, h12, h13, A10, A11, A12, A13, Wf1.x, Wf1.y,
                 0.f, 0.f, 0.f, 0.f);
        h00 = fmaxf(h00, 0.f); h01 = fmaxf(h01, 0.f);
        h02 = fmaxf(h02, 0.f); h03 = fmaxf(h03, 0.f);
        h10 = fmaxf(h10, 0.f); h11 = fmaxf(h11, 0.f);
        h12 = fmaxf(h12, 0.f); h13 = fmaxf(h13, 0.f);

        /* hidden-D frag == Q-mma A frag (register chain, no smem) */
        uint32_t qa0 = cvt_f16x2(h01, h00);
        uint32_t qa1 = cvt_f16x2(h03, h02);
        uint32_t qa2 = cvt_f16x2(h11, h10);
        uint32_t qa3 = cvt_f16x2(h13, h12);

        /* Q head: 3 n-tiles of m16n8k16, K = 16 (2 gvfs x 8 hidden) */
        const char* qb = chb + Q_RELB + p * 768;
        uint2 Qf0 = *(const uint2*)(qb + lane * 8);
        uint2 Qf1 = *(const uint2*)(qb + 256 + lane * 8);
        uint2 Qf2 = *(const uint2*)(qb + 512 + lane * 8);
        mma16816(D00, D01, D02, D03, qa0, qa1, qa2, qa3, Qf0.x, Qf0.y,
                 D00, D01, D02, D03);
        mma16816(D10, D11, D12, D13, qa0, qa1, qa2, qa3, Qf1.x, Qf1.y,
                 D10, D11, D12, D13);
        mma16816(D20, D21, D22, D23, qa0, qa1, qa2, qa3, Qf2.x, Qf2.y,
                 D20, D21, D22, D23);

        set_bar(1 + set);
        if (producer && c + NBUF < NCH) {
            fence_async();
            mbar_expect_tx(MBf + (uint32_t)b * 8u, CH_BYTES);
            bulk_g2s(CHB + (uint32_t)b * CH_BYTES,
                     SRC + (size_t)(c + NBUF) * CHW32, CH_BYTES,
                     MBf + (uint32_t)b * 8u);
        }
    }

    /* store per-warp D partials: P[w][r][a], a = tile*8 + 2t(+1), r = g(+8) */
    {
        float* P = (float*)(smb + P_B) + w * (ROWS * 24);
        P[(g    ) * 24 + 2 * t     + 0] = D00;
        P[(g    ) * 24 + 2 * t + 1 + 0] = D01;
        P[(g + 8) * 24 + 2 * t     + 0] = D02;
        P[(g + 8) * 24 + 2 * t + 1 + 0] = D03;
        P[(g    ) * 24 + 2 * t     + 8] = D10;
        P[(g    ) * 24 + 2 * t + 1 + 8] = D11;
        P[(g + 8) * 24 + 2 * t     + 8] = D12;
        P[(g + 8) * 24 + 2 * t + 1 + 8] = D13;
        P[(g    ) * 24 + 2 * t     + 16] = D20;
        P[(g    ) * 24 + 2 * t + 1 + 16] = D21;
        P[(g + 8) * 24 + 2 * t     + 16] = D22;
        P[(g + 8) * 24 + 2 * t + 1 + 16] = D23;
    }
    __syncthreads();   /* chunk buffers now reusable for tail */

    /* ---- obs-direct Q tail: TMA-staged fp32 slices (R8-proven) ---- */
    {
        uint32_t TB0 = sbase + (uint32_t)CH_B;
        if (tid == 0) {
            mbar_expect_tx(MT[0], QO_BYTES);
            bulk_g2s(TB0, QobsPk_g, QO_BYTES, MT[0]);
            mbar_expect_tx(MT[1], QO_BYTES);
            bulk_g2s(TB0 + QO_BYTES, QobsPk_g + QO_SLICE, QO_BYTES, MT[1]);
        }

        ull oacc[9];
        #pragma unroll
        for (int a2 = 0; a2 < 9; ++a2) oacc[a2] = 0ull;
        const float* orow = obs + (size_t)(r0 + w) * OBS_DIMV;

        #pragma unroll 1
        for (int s = 0; s < NSLICE; ++s) {
            mbar_wait(MT[s & 1], (s >> 1) & 1);
            __syncthreads();
            if (tid == 0 && s >= 1 && s + 1 < NSLICE) {
                int b2 = (s + 1) & 1;
                fence_async();
                mbar_expect_tx(MT[b2], QO_BYTES);
                bulk_g2s(TB0 + (uint32_t)b2 * QO_BYTES,
                         QobsPk_g + (size_t)(s + 1) * QO_SLICE, QO_BYTES, MT[b2]);
            }
            const float* qs = (const float*)(smb + CH_B) + (s & 1) * QO_SLICE;
            #pragma unroll
            for (int jj = 0; jj < 4; ++jj) {
                int jloc = jj * 64 + lane * 2;
                float2 ov = *(const float2*)(orow + s * QO_COLS + jloc);
                ull oA = pack2(ov.x, ov.x);
                ull oB = pack2(ov.y, ov.y);
                #pragma unroll
                for (int a2 = 0; a2 < 9; ++a2) {
                    ulonglong2 qv = *(const ulonglong2*)(qs + a2 * (QO_COLS * 2) + jloc * 2);
                    ffma2(oacc[a2], qv.x, oA);
                    ffma2(oacc[a2], qv.y, oB);
                }
            }
        }

        #pragma unroll
        for (int a2 = 0; a2 < 9; ++a2) {
            #pragma unroll
            for (int off = 16; off >= 1; off >>= 1) {
                ull o = __shfl_xor_sync(0xffffffffu, oacc[a2], off);
                oacc[a2] = addf2(oacc[a2], o);
            }
        }
        if (lane == 0) {
            float* Po = (float*)(smb + POBS_B) + w * NA;
            #pragma unroll
            for (int a2 = 0; a2 < 9; ++a2) {
                float2 v = unpack2(oacc[a2]);
                Po[2 * a2]     = v.x;
                Po[2 * a2 + 1] = v.y;
            }
        }
    }
    __syncthreads();

    /* final: 288 threads sum 16 warp partials + obs partial */
    if (tid < ROWS * NA) {
        int rr = tid / NA;
        int a  = tid - rr * NA;
        const float* P = (const float*)(smb + P_B);
        float s = 0.f;
        #pragma unroll
        for (int pw = 0; pw < NWARP; ++pw)
            s += P[pw * (ROWS * 24) + rr * 24 + a];
        s += ((const float*)(smb + POBS_B))[rr * NA + a];
        out[(size_t)(r0 + rr) * NA + a] = s;
    }
}

extern "C" void kernel_launch(void* const* d_in, const int* in_sizes, int n_in,
                              void* d_out, int out_size)
{
    const float* obs  = (const float*)d_in[0];
    const float* gvfW = (const float*)d_in[1];
    const float* qW   = (const float*)d_in[2];
    const int*   gidx = (const int*)d_in[3];
    float* out = (float*)d_out;

    repack_kernel<<<(N_TOT + 255) / 256, 256>>>(gvfW, qW, gidx);

    cudaFuncSetAttribute(nibbler_main,
                         cudaFuncAttributeMaxDynamicSharedMemorySize, SMEM_BYTES);
    nibbler_main<<<2048 / ROWS, THREADS, SMEM_BYTES>>>(obs, out);
}

// round 13
// speedup vs baseline: 6.2486x; 1.0579x over previous
#include <cuda_runtime.h>
#include <cuda_fp16.h>
#include <cstdint>

typedef unsigned long long ull;

#define OBS_DIMV 4096
#define NGVF     4096
#define NA       18
#define TF       36864
#define ROWS     16
#define THREADS  512
#define NWARP    16
#define PAIRS    8
#define OSTRIDE_H2 4100          /* half2 words per pair-row (4096 + 4 pad) */

/* 8-gvf chunks, 4 warp-sets (4 warps each), 3 buffers per set */
#define NSET     4
#define NBUF     3
#define NCH      128             /* chunks per set */
/* chunk layout (u32 words): idx 128 | W 512 | Q 768  = 1408 words = 5632 B */
#define CHW32    1408
#define CH_BYTES (CHW32 * 4)
#define W_RELB   512
#define Q_RELB   2560

/* obs-direct tail slices (fp32) */
#define QO_COLS  256
#define QO_SLICE 4608            /* floats */
#define QO_BYTES (QO_SLICE * 4)
#define NSLICE   (OBS_DIMV / QO_COLS)

/* smem byte offsets */
#define OBS_B    0
#define OBS_BYTES (PAIRS * OSTRIDE_H2 * 4)        /* 131200 */
#define CH_B     OBS_BYTES                        /* 12 bufs x 5632 = 67584 */
#define P_B      (CH_B + NSET * NBUF * CH_BYTES)  /* 198784 */
#define P_BYTES  (NWARP * ROWS * 24 * 4)          /* 24576  */
#define POBS_B   (P_B + P_BYTES)                  /* 223360 */
#define POBS_BYTES (NWARP * NA * 4)               /* 1152   */
#define MBAR_B   (POBS_B + POBS_BYTES)            /* 224512 */
#define SMEM_BYTES (MBAR_B + 128)                 /* 224640 <= 232448 */

/* ---- repacked weights (rebuilt every launch) ---- */
__device__ __align__(16) uint32_t ChunkPk_g[(size_t)NSET * NCH * CHW32]; /* 2.88MB */
__device__ __align__(16) float    QobsPk_g[NSLICE * QO_SLICE];

#define N_CHW (NSET * NCH * CHW32)
#define N_QO  (NSLICE * QO_SLICE)
#define N_TOT (N_CHW + N_QO)

__global__ void repack_kernel(const float* __restrict__ gvfW,
                              const float* __restrict__ qW,
                              const int*   __restrict__ gidx)
{
    int id = blockIdx.x * 256 + threadIdx.x;
    if (id < N_CHW) {
        int sc = id / CHW32;
        int r  = id - sc * CHW32;
        int gbase = (sc >> 7) * 1024 + (sc & 127) * 8;
        uint32_t val;
        if (r < 128) {
            int g = r >> 4, t = (r >> 2) & 3, comp = r & 3;
            int i = (comp < 2) ? (2 * t + comp) : (2 * t + 8 + (comp - 2));
            val = (uint32_t)(gidx[(gbase + g) * 16 + i] * 4);
        } else if (r < 640) {
            int w2 = r - 128;
            int g = w2 >> 6, rem = w2 & 63;
            int lane = rem >> 1, half = rem & 1;
            int h = lane >> 2, t = lane & 3;
            int k0 = half ? (2 * t + 8) : (2 * t);
            float f0 = gvfW[((size_t)(gbase + g) * 8 + h) * 16 + k0];
            float f1 = gvfW[((size_t)(gbase + g) * 8 + h) * 16 + k0 + 1];
            __half2 hh = __floats2half2_rn(f0, f1);
            val = *reinterpret_cast<uint32_t*>(&hh);
        } else {
            int qd = r - 640;
            int p = qd / 192, rem = qd - p * 192;
            int tile = rem >> 6, rem2 = rem & 63;
            int lane = rem2 >> 1, half = rem2 & 1;
            int n = (lane >> 2) + tile * 8, t = lane & 3;
            int k0 = half ? (2 * t + 8) : (2 * t);
            float q0 = 0.f, q1 = 0.f;
            if (n < 18) {
                int gv = gbase + p * 2 + (k0 >> 3);
                int h0 = k0 & 7;
                q0 = qW[(size_t)n * TF + OBS_DIMV + (size_t)gv * 8 + h0];
                q1 = qW[(size_t)n * TF + OBS_DIMV + (size_t)gv * 8 + h0 + 1];
            }
            __half2 hh = __floats2half2_rn(q0, q1);
            val = *reinterpret_cast<uint32_t*>(&hh);
        }
        ChunkPk_g[id] = val;
    } else if (id < N_TOT) {
        int t = id - N_CHW;
        int s = t / QO_SLICE, r = t - s * QO_SLICE;
        int a2 = r >> 9, u = r & 511, col = u >> 1, sp = u & 1;
        QobsPk_g[t] = qW[(size_t)(2 * a2 + sp) * TF + s * QO_COLS + col];
    }
}

/* ---- mbarrier + bulk-TMA helpers ---- */
__device__ __forceinline__ void mbar_init(uint32_t mbar, uint32_t cnt) {
    asm volatile("mbarrier.init.shared.b64 [%0], %1;" :: "r"(mbar), "r"(cnt) : "memory");
}
__device__ __forceinline__ void mbar_expect_tx(uint32_t mbar, uint32_t bytes) {
    asm volatile("mbarrier.arrive.expect_tx.shared.b64 _, [%0], %1;"
                 :: "r"(mbar), "r"(bytes) : "memory");
}
__device__ __forceinline__ void bulk_g2s(uint32_t dst, const void* src,
                                         uint32_t bytes, uint32_t mbar) {
    asm volatile("cp.async.bulk.shared::cta.global.mbarrier::complete_tx::bytes "
                 "[%0], [%1], %2, [%3];"
                 :: "r"(dst), "l"(src), "r"(bytes), "r"(mbar) : "memory");
}
__device__ __forceinline__ void mbar_wait(uint32_t mbar, uint32_t parity) {
    asm volatile(
        "{\n\t"
        ".reg .pred P;\n"
        "LW_%=:\n\t"
        "mbarrier.try_wait.parity.acquire.cta.shared::cta.b64 P, [%0], %1, 0x989680;\n\t"
        "@P bra.uni LD_%=;\n\t"
        "bra.uni LW_%=;\n"
        "LD_%=:\n\t"
        "}"
        :: "r"(mbar), "r"(parity) : "memory");
}
__device__ __forceinline__ void set_bar(int id) {
    asm volatile("bar.sync %0, 128;" :: "r"(id) : "memory");
}
__device__ __forceinline__ void fence_async() {
    asm volatile("fence.proxy.async.shared::cta;" ::: "memory");
}

/* ---- mma + cvt helpers ---- */
__device__ __forceinline__ void mma16816(float& d0, float& d1, float& d2, float& d3,
    uint32_t a0, uint32_t a1, uint32_t a2, uint32_t a3,
    uint32_t b0, uint32_t b1,
    float c0, float c1, float c2, float c3)
{
    asm volatile("mma.sync.aligned.m16n8k16.row.col.f32.f16.f16.f32 "
        "{%0,%1,%2,%3},{%4,%5,%6,%7},{%8,%9},{%10,%11,%12,%13};"
        : "=f"(d0), "=f"(d1), "=f"(d2), "=f"(d3)
        : "r"(a0), "r"(a1), "r"(a2), "r"(a3), "r"(b0), "r"(b1),
          "f"(c0), "f"(c1), "f"(c2), "f"(c3));
}
__device__ __forceinline__ uint32_t cvt_f16x2(float hi, float lo) {
    uint32_t r; asm("cvt.rn.f16x2.f32 %0, %1, %2;" : "=r"(r) : "f"(hi), "f"(lo)); return r;
}
__device__ __forceinline__ uint32_t hmax2_z(uint32_t v) {
    uint32_t r; asm("max.f16x2 %0, %1, %2;" : "=r"(r) : "r"(v), "r"(0u)); return r;
}

/* ---- f32x2 helpers (tail only) ---- */
__device__ __forceinline__ ull pack2(float a, float b) {
    ull r; asm("mov.b64 %0,{%1,%2};" : "=l"(r) : "f"(a), "f"(b)); return r;
}
__device__ __forceinline__ float2 unpack2(ull v) {
    float2 f; asm("mov.b64 {%0,%1},%2;" : "=f"(f.x), "=f"(f.y) : "l"(v)); return f;
}
__device__ __forceinline__ void ffma2(ull& d, ull a, ull b) {
    asm("fma.rn.f32x2 %0,%1,%2,%0;" : "+l"(d) : "l"(a), "l"(b));
}
__device__ __forceinline__ ull addf2(ull a, ull b) {
    ull r; asm("add.rn.f32x2 %0,%1,%2;" : "=l"(r) : "l"(a), "l"(b)); return r;
}

extern __shared__ float smf[];

__global__ void __launch_bounds__(THREADS, 1)
nibbler_main(const float* __restrict__ obs, float* __restrict__ out)
{
    const int tid  = threadIdx.x;
    const int w    = tid >> 5;
    const int lane = tid & 31;
    const int set  = w >> 2;
    const int p    = w & 3;
    const int g    = lane >> 2;
    const int t    = lane & 3;
    const int r0   = blockIdx.x * ROWS;

    char* smb = (char*)smf;
    uint32_t sbase = (uint32_t)__cvta_generic_to_shared(smf);
    const uint32_t MBASE = sbase + MBAR_B;
    const uint32_t MT[2] = { MBASE + 96u, MBASE + 104u };

    if (tid == 0) {
        #pragma unroll
        for (int i = 0; i < NSET * NBUF; ++i) mbar_init(MBASE + (uint32_t)i * 8u, 1);
        mbar_init(MT[0], 1);
        mbar_init(MT[1], 1);
    }
    __syncthreads();

    const bool producer = (tid == set * 128);
    const uint32_t MBf = MBASE + (uint32_t)(set * NBUF) * 8u;
    const uint32_t CHB = sbase + (uint32_t)(CH_B + set * NBUF * CH_BYTES);
    const uint32_t* SRC = ChunkPk_g + (size_t)set * NCH * CHW32;

    if (producer) {
        #pragma unroll
        for (int b = 0; b < NBUF; ++b) {
            mbar_expect_tx(MBf + (uint32_t)b * 8u, CH_BYTES);
            bulk_g2s(CHB + (uint32_t)b * CH_BYTES, SRC + (size_t)b * CHW32,
                     CH_BYTES, MBf + (uint32_t)b * 8u);
        }
    }

    /* stage obs as half2 row-pairs (row pp low, row pp+8 high) */
    {
        __half2* sObs = reinterpret_cast<__half2*>(smf);
        #pragma unroll 4
        for (int id = tid; id < PAIRS * (OBS_DIMV / 4); id += THREADS) {
            int pp = id >> 10, j = id & 1023;
            float4 va = *(const float4*)(obs + (size_t)(r0 + pp    ) * OBS_DIMV + j * 4);
            float4 vb = *(const float4*)(obs + (size_t)(r0 + pp + 8) * OBS_DIMV + j * 4);
            __half2 h0 = __floats2half2_rn(va.x, vb.x);
            __half2 h1 = __floats2half2_rn(va.y, vb.y);
            __half2 h2 = __floats2half2_rn(va.z, vb.z);
            __half2 h3 = __floats2half2_rn(va.w, vb.w);
            uint4 pk;
            pk.x = *reinterpret_cast<uint32_t*>(&h0);
            pk.y = *reinterpret_cast<uint32_t*>(&h1);
            pk.z = *reinterpret_cast<uint32_t*>(&h2);
            pk.w = *reinterpret_cast<uint32_t*>(&h3);
            *(uint4*)(sObs + pp * OSTRIDE_H2 + j * 4) = pk;
        }
    }
    __syncthreads();

    const char* obp = smb + g * (OSTRIDE_H2 * 4);

    float D00 = 0.f, D01 = 0.f, D02 = 0.f, D03 = 0.f;
    float D10 = 0.f, D11 = 0.f, D12 = 0.f, D13 = 0.f;
    float D20 = 0.f, D21 = 0.f, D22 = 0.f, D23 = 0.f;

/* per-half compute macro: gathers, Q-frag load, prefetch of next idx+W,
   set-barrier, producer restage, mma chain */
#define HALF_BODY(CC, IVA0, IVA1, WFA0, WFA1, IVB0, IVB1, WFB0, WFB1)            \
    {                                                                            \
        const int b_   = (CC) % NBUF;                                            \
        const char* chb_ = smb + CH_B + (set * NBUF + b_) * CH_BYTES;            \
        /* gathers for chunk CC (uses prefetched idx) */                         \
        uint32_t wa = *(const uint32_t*)(obp + IVA0.x);                          \
        uint32_t wb = *(const uint32_t*)(obp + IVA0.y);                          \
        uint32_t wc = *(const uint32_t*)(obp + IVA0.z);                          \
        uint32_t wd = *(const uint32_t*)(obp + IVA0.w);                          \
        uint32_t xa = *(const uint32_t*)(obp + IVA1.x);                          \
        uint32_t xb = *(const uint32_t*)(obp + IVA1.y);                          \
        uint32_t xc = *(const uint32_t*)(obp + IVA1.z);                          \
        uint32_t xd = *(const uint32_t*)(obp + IVA1.w);                          \
        /* Q frags for chunk CC (early: latency hidden behind hidden mma) */     \
        const char* qb_ = chb_ + Q_RELB + p * 768;                               \
        uint2 Qf0 = *(const uint2*)(qb_ + lane * 8);                             \
        uint2 Qf1 = *(const uint2*)(qb_ + 256 + lane * 8);                       \
        uint2 Qf2 = *(const uint2*)(qb_ + 512 + lane * 8);                       \
        /* prefetch idx+W frags for chunk CC+1 */                                \
        if ((CC) + 1 < NCH) {                                                    \
            const int bn_ = ((CC) + 1) % NBUF;                                   \
            mbar_wait(MBf + (uint32_t)bn_ * 8u, (((CC) + 1) / NBUF) & 1);        \
            const char* chn_ = smb + CH_B + (set * NBUF + bn_) * CH_BYTES;       \
            IVB0 = ((const int4*)chn_)[(2 * p) * 4 + t];                         \
            IVB1 = ((const int4*)chn_)[(2 * p + 1) * 4 + t];                     \
            WFB0 = *(const uint2*)(chn_ + W_RELB + (2 * p) * 256 + lane * 8);    \
            WFB1 = *(const uint2*)(chn_ + W_RELB + (2 * p + 1) * 256 + lane * 8);\
        }                                                                        \
        /* all reads of buffer b_ complete across the 4 set warps */             \
        set_bar(1 + set);                                                        \
        if (producer && (CC) + NBUF < NCH) {                                     \
            fence_async();                                                       \
            mbar_expect_tx(MBf + (uint32_t)b_ * 8u, CH_BYTES);                   \
            bulk_g2s(CHB + (uint32_t)b_ * CH_BYTES,                              \
                     SRC + (size_t)((CC) + NBUF) * CHW32, CH_BYTES,              \
                     MBf + (uint32_t)b_ * 8u);                                   \
        }                                                                        \
        /* A-fragment build */                                                   \
        uint32_t A00 = __byte_perm(wa, wb, 0x5410);                              \
        uint32_t A01 = __byte_perm(wa, wb, 0x7632);                              \
        uint32_t A02 = __byte_perm(wc, wd, 0x5410);                              \
        uint32_t A03 = __byte_perm(wc, wd, 0x7632);                              \
        uint32_t A10 = __byte_perm(xa, xb, 0x5410);                              \
        uint32_t A11 = __byte_perm(xa, xb, 0x7632);                              \
        uint32_t A12 = __byte_perm(xc, xd, 0x5410);                              \
        uint32_t A13 = __byte_perm(xc, xd, 0x7632);                              \
        float h00, h01, h02, h03, h10, h11, h12, h13;                            \
        mma16816(h00, h01, h02, h03, A00, A01, A02, A03, WFA0.x, WFA0.y,         \
                 0.f, 0.f, 0.f, 0.f);                                            \
        mma16816(h10, h11, h12, h13, A10, A11, A12, A13, WFA1.x, WFA1.y,         \
                 0.f, 0.f, 0.f, 0.f);                                            \
        uint32_t qa0 = hmax2_z(cvt_f16x2(h01, h00));                             \
        uint32_t qa1 = hmax2_z(cvt_f16x2(h03, h02));                             \
        uint32_t qa2 = hmax2_z(cvt_f16x2(h11, h10));                             \
        uint32_t qa3 = hmax2_z(cvt_f16x2(h13, h12));                             \
        mma16816(D00, D01, D02, D03, qa0, qa1, qa2, qa3, Qf0.x, Qf0.y,           \
                 D00, D01, D02, D03);                                            \
        mma16816(D10, D11, D12, D13, qa0, qa1, qa2, qa3, Qf1.x, Qf1.y,           \
                 D10, D11, D12, D13);                                            \
        mma16816(D20, D21, D22, D23, qa0, qa1, qa2, qa3, Qf2.x, Qf2.y,           \
                 D20, D21, D22, D23);                                            \
    }

    /* preamble: load idx+W frags of chunk 0 */
    int4 ivA0, ivA1, ivB0, ivB1;
    uint2 WfA0, WfA1, WfB0, WfB1;
    {
        mbar_wait(MBf, 0);
        const char* ch0 = smb + CH_B + (set * NBUF) * CH_BYTES;
        ivA0 = ((const int4*)ch0)[(2 * p) * 4 + t];
        ivA1 = ((const int4*)ch0)[(2 * p + 1) * 4 + t];
        WfA0 = *(const uint2*)(ch0 + W_RELB + (2 * p) * 256 + lane * 8);
        WfA1 = *(const uint2*)(ch0 + W_RELB + (2 * p + 1) * 256 + lane * 8);
    }

    #pragma unroll 1
    for (int c = 0; c < NCH; c += 2) {
        HALF_BODY(c,     ivA0, ivA1, WfA0, WfA1, ivB0, ivB1, WfB0, WfB1)
        HALF_BODY(c + 1, ivB0, ivB1, WfB0, WfB1, ivA0, ivA1, WfA0, WfA1)
    }
#undef HALF_BODY

    /* store per-warp D partials */
    {
        float* P = (float*)(smb + P_B) + w * (ROWS * 24);
        P[(g    ) * 24 + 2 * t     + 0] = D00;
        P[(g    ) * 24 + 2 * t + 1 + 0] = D01;
        P[(g + 8) * 24 + 2 * t     + 0] = D02;
        P[(g + 8) * 24 + 2 * t + 1 + 0] = D03;
        P[(g    ) * 24 + 2 * t     + 8] = D10;
        P[(g    ) * 24 + 2 * t + 1 + 8] = D11;
        P[(g + 8) * 24 + 2 * t     + 8] = D12;
        P[(g + 8) * 24 + 2 * t + 1 + 8] = D13;
        P[(g    ) * 24 + 2 * t     + 16] = D20;
        P[(g    ) * 24 + 2 * t + 1 + 16] = D21;
        P[(g + 8) * 24 + 2 * t     + 16] = D22;
        P[(g + 8) * 24 + 2 * t + 1 + 16] = D23;
    }
    __syncthreads();

    /* ---- obs-direct Q tail: TMA-staged fp32 slices ---- */
    {
        uint32_t TB0 = sbase + (uint32_t)CH_B;
        if (tid == 0) {
            mbar_expect_tx(MT[0], QO_BYTES);
            bulk_g2s(TB0, QobsPk_g, QO_BYTES, MT[0]);
            mbar_expect_tx(MT[1], QO_BYTES);
            bulk_g2s(TB0 + QO_BYTES, QobsPk_g + QO_SLICE, QO_BYTES, MT[1]);
        }

        ull oacc[9];
        #pragma unroll
        for (int a2 = 0; a2 < 9; ++a2) oacc[a2] = 0ull;
        const float* orow = obs + (size_t)(r0 + w) * OBS_DIMV;

        #pragma unroll 1
        for (int s = 0; s < NSLICE; ++s) {
            mbar_wait(MT[s & 1], (s >> 1) & 1);
            __syncthreads();
            if (tid == 0 && s >= 1 && s + 1 < NSLICE) {
                int b2 = (s + 1) & 1;
                fence_async();
                mbar_expect_tx(MT[b2], QO_BYTES);
                bulk_g2s(TB0 + (uint32_t)b2 * QO_BYTES,
                         QobsPk_g + (size_t)(s + 1) * QO_SLICE, QO_BYTES, MT[b2]);
            }
            const float* qs = (const float*)(smb + CH_B) + (s & 1) * QO_SLICE;
            #pragma unroll
            for (int jj = 0; jj < 4; ++jj) {
                int jloc = jj * 64 + lane * 2;
                float2 ov = *(const float2*)(orow + s * QO_COLS + jloc);
                ull oA = pack2(ov.x, ov.x);
                ull oB = pack2(ov.y, ov.y);
                #pragma unroll
                for (int a2 = 0; a2 < 9; ++a2) {
                    ulonglong2 qv = *(const ulonglong2*)(qs + a2 * (QO_COLS * 2) + jloc * 2);
                    ffma2(oacc[a2], qv.x, oA);
                    ffma2(oacc[a2], qv.y, oB);
                }
            }
        }

        #pragma unroll
        for (int a2 = 0; a2 < 9; ++a2) {
            #pragma unroll
            for (int off = 16; off >= 1; off >>= 1) {
                ull o = __shfl_xor_sync(0xffffffffu, oacc[a2], off);
                oacc[a2] = addf2(oacc[a2], o);
            }
        }
        if (lane == 0) {
            float* Po = (float*)(smb + POBS_B) + w * NA;
            #pragma unroll
            for (int a2 = 0; a2 < 9; ++a2) {
                float2 v = unpack2(oacc[a2]);
                Po[2 * a2]     = v.x;
                Po[2 * a2 + 1] = v.y;
            }
        }
    }
    __syncthreads();

    /* final: 288 threads sum 16 warp partials + obs partial */
    if (tid < ROWS * NA) {
        int rr = tid / NA;
        int a  = tid - rr * NA;
        const float* P = (const float*)(smb + P_B);
        float s = 0.f;
        #pragma unroll
        for (int pw = 0; pw < NWARP; ++pw)
            s += P[pw * (ROWS * 24) + rr * 24 + a];
        s += ((const float*)(smb + POBS_B))[rr * NA + a];
        out[(size_t)(r0 + rr) * NA + a] = s;
    }
}

extern "C" void kernel_launch(void* const* d_in, const int* in_sizes, int n_in,
                              void* d_out, int out_size)
{
    const float* obs  = (const float*)d_in[0];
    const float* gvfW = (const float*)d_in[1];
    const float* qW   = (const float*)d_in[2];
    const int*   gidx = (const int*)d_in[3];
    float* out = (float*)d_out;

    repack_kernel<<<(N_TOT + 255) / 256, 256>>>(gvfW, qW, gidx);

    cudaFuncSetAttribute(nibbler_main,
                         cudaFuncAttributeMaxDynamicSharedMemorySize, SMEM_BYTES);
    nibbler_main<<<2048 / ROWS, THREADS, SMEM_BYTES>>>(obs, out);
}